// round 1
// baseline (speedup 1.0000x reference)
#include <cuda_runtime.h>
#include <math.h>
#include <float.h>

#define BATCH   2
#define SEQ     2048
#define HID     2048
#define NHEADS  16
#define HD      128

// ---------------- static scratch (no allocations allowed) ----------------
__device__ float g_qkv [BATCH * SEQ * 3 * HID];       // [B,S,3H]   ~100.7 MB
__device__ float g_Q   [BATCH * NHEADS * SEQ * HD];   // [B,NH,S,D]  ~33.5 MB
__device__ float g_K   [BATCH * NHEADS * SEQ * HD];
__device__ float g_V   [BATCH * NHEADS * SEQ * HD];
__device__ float g_ctx [BATCH * SEQ * HID];           // [B,S,H]
__device__ float g_bias[NHEADS * SEQ];                // bias[h][q-k]

// ---------------- fp32 tiled GEMM: C[M,N] = A[M,K] @ B[K,N] ----------------
// 128x128 block tile, BK=8, 256 threads, 8x8 per-thread tile.
__global__ __launch_bounds__(256) void sgemm128(
    const float* __restrict__ A, const float* __restrict__ B,
    float* __restrict__ C, int M, int N, int K)
{
    __shared__ float As[8][128];   // transposed: As[k][m]
    __shared__ float Bs[8][128];

    const int tid  = threadIdx.x;
    const int row0 = blockIdx.y * 128;
    const int col0 = blockIdx.x * 128;

    const int aRow = tid >> 1;            // 0..127
    const int aCol = (tid & 1) * 4;       // 0 or 4
    const int bRow = tid >> 5;            // 0..7
    const int bCol = (tid & 31) * 4;      // 0..124

    const int tx = tid & 15;              // 0..15  -> col  tx*8
    const int ty = tid >> 4;              // 0..15  -> row  ty*8

    float acc[8][8];
#pragma unroll
    for (int i = 0; i < 8; i++)
#pragma unroll
        for (int j = 0; j < 8; j++) acc[i][j] = 0.f;

    const float* Aptr = A + (size_t)(row0 + aRow) * K + aCol;
    const float* Bptr = B + (size_t)bRow * N + col0 + bCol;

    for (int k0 = 0; k0 < K; k0 += 8) {
        float4 a4 = *(const float4*)(Aptr + k0);
        float4 b4 = *(const float4*)(Bptr + (size_t)k0 * N);
        __syncthreads();
        As[aCol + 0][aRow] = a4.x;
        As[aCol + 1][aRow] = a4.y;
        As[aCol + 2][aRow] = a4.z;
        As[aCol + 3][aRow] = a4.w;
        *(float4*)&Bs[bRow][bCol] = b4;
        __syncthreads();
#pragma unroll
        for (int kk = 0; kk < 8; kk++) {
            float ra[8], rb[8];
#pragma unroll
            for (int i = 0; i < 8; i++) ra[i] = As[kk][ty * 8 + i];
#pragma unroll
            for (int j = 0; j < 8; j++) rb[j] = Bs[kk][tx * 8 + j];
#pragma unroll
            for (int i = 0; i < 8; i++)
#pragma unroll
                for (int j = 0; j < 8; j++)
                    acc[i][j] += ra[i] * rb[j];
        }
    }

#pragma unroll
    for (int i = 0; i < 8; i++) {
        float* Crow = C + (size_t)(row0 + ty * 8 + i) * N + col0 + tx * 8;
        *(float4*)(Crow)     = make_float4(acc[i][0], acc[i][1], acc[i][2], acc[i][3]);
        *(float4*)(Crow + 4) = make_float4(acc[i][4], acc[i][5], acc[i][6], acc[i][7]);
    }
}

// ---------------- RoPE + split to [B,NH,S,D] layout ----------------
__global__ __launch_bounds__(256) void rope_split_kernel()
{
    int t = blockIdx.x * blockDim.x + threadIdx.x;      // B*S*NH*64 threads
    int d = t & 63;
    int h = (t >> 6) & (NHEADS - 1);
    int s = (t >> 10) & (SEQ - 1);
    int b = t >> 21;

    const float* base = g_qkv + ((size_t)(b * SEQ + s)) * (3 * HID) + h * HD;
    float q1 = base[d],            q2 = base[d + 64];
    float k1 = base[HID + d],      k2 = base[HID + d + 64];
    float v1 = base[2 * HID + d],  v2 = base[2 * HID + d + 64];

    float inv  = powf(10000.f, -(float)d * (1.f / 64.f));
    float ang  = (float)s * inv;
    float sn, cs;
    sincosf(ang, &sn, &cs);

    size_t o = ((size_t)((b * NHEADS + h) * SEQ + s)) * HD;
    g_Q[o + d]      = q1 * cs - q2 * sn;
    g_Q[o + d + 64] = q2 * cs + q1 * sn;
    g_K[o + d]      = k1 * cs - k2 * sn;
    g_K[o + d + 64] = k2 * cs + k1 * sn;
    g_V[o + d]      = v1;
    g_V[o + d + 64] = v2;
}

// ---------------- relative-position bias table ----------------
__global__ void bias_kernel(const float* __restrict__ rel)
{
    int idx = blockIdx.x * blockDim.x + threadIdx.x;    // NHEADS*SEQ
    if (idx >= NHEADS * SEQ) return;
    int h = idx >> 11;
    int n = idx & (SEQ - 1);
    int bucket;
    if (n < 16) {
        bucket = n;
    } else {
        float val = logf((float)n * (1.f / 16.f)) / logf(8.f) * 16.f;
        int bi = (int)val + 16;
        bucket = bi < 31 ? bi : 31;
    }
    g_bias[idx] = rel[bucket * NHEADS + h];
}

// ---------------- flash attention (fp32, causal, +bias) ----------------
// grid (S/64, NH, B), 256 threads. Warp w owns q rows w*8..w*8+7.
// Lane owns k cols {2*lane, 2*lane+1} for scores and d cols lane*4..+3 for O.
#define QPITCH 132
#define PPITCH 66
#define FLASH_SMEM ((3 * 64 * QPITCH + 64 * PPITCH) * 4)

__global__ __launch_bounds__(256, 1) void flash_kernel()
{
    extern __shared__ float sm[];
    float* Qs = sm;
    float* Ks = Qs + 64 * QPITCH;
    float* Vs = Ks + 64 * QPITCH;
    float* Ps = Vs + 64 * QPITCH;

    const int qt  = blockIdx.x;
    const int h   = blockIdx.y;
    const int b   = blockIdx.z;
    const int tid = threadIdx.x;
    const int warp = tid >> 5, lane = tid & 31;

    const size_t headBase = (size_t)(b * NHEADS + h) * SEQ * HD;
    const float* Qg = g_Q + headBase + (size_t)qt * 64 * HD;

    // load Q tile (64x128)
    for (int f = tid; f < 2048; f += 256) {
        int r = f >> 5, c4 = f & 31;
        *(float4*)(Qs + r * QPITCH + c4 * 4) = *(const float4*)(Qg + r * HD + c4 * 4);
    }

    const int r0 = warp * 8;
    const int c0 = lane * 2, c1 = c0 + 1;
    const float scale = 0.08838834764831845f;   // 1/sqrt(128)
    const float* biasH = g_bias + h * SEQ;

    float m[8], l[8];
    float4 o[8];
#pragma unroll
    for (int i = 0; i < 8; i++) {
        m[i] = -INFINITY; l[i] = 0.f;
        o[i] = make_float4(0.f, 0.f, 0.f, 0.f);
    }

    for (int kt = 0; kt <= qt; ++kt) {
        __syncthreads();
        const float* Kg = g_K + headBase + (size_t)kt * 64 * HD;
        const float* Vg = g_V + headBase + (size_t)kt * 64 * HD;
        for (int f = tid; f < 2048; f += 256) {
            int r = f >> 5, c4 = f & 31;
            *(float4*)(Ks + r * QPITCH + c4 * 4) = *(const float4*)(Kg + r * HD + c4 * 4);
            *(float4*)(Vs + r * QPITCH + c4 * 4) = *(const float4*)(Vg + r * HD + c4 * 4);
        }
        __syncthreads();

        // --- scores: s[i][2] = Q[r0+i] . K[c]
        float s0[8], s1[8];
#pragma unroll
        for (int i = 0; i < 8; i++) { s0[i] = 0.f; s1[i] = 0.f; }
        const float* K0 = Ks + c0 * QPITCH;
        const float* K1 = Ks + c1 * QPITCH;
#pragma unroll 8
        for (int d4 = 0; d4 < 32; ++d4) {
            float4 k0 = *(const float4*)(K0 + d4 * 4);
            float4 k1 = *(const float4*)(K1 + d4 * 4);
#pragma unroll
            for (int i = 0; i < 8; i++) {
                float4 q = *(const float4*)(Qs + (r0 + i) * QPITCH + d4 * 4);
                s0[i] += q.x * k0.x + q.y * k0.y + q.z * k0.z + q.w * k0.w;
                s1[i] += q.x * k1.x + q.y * k1.y + q.z * k1.z + q.w * k1.w;
            }
        }

        // --- online softmax per row
        const int kc0 = kt * 64 + c0;
        const int kc1 = kc0 + 1;
#pragma unroll
        for (int i = 0; i < 8; i++) {
            int qr = qt * 64 + r0 + i;
            float v0 = (kc0 <= qr) ? (s0[i] * scale + biasH[qr - kc0]) : -INFINITY;
            float v1 = (kc1 <= qr) ? (s1[i] * scale + biasH[qr - kc1]) : -INFINITY;
            float mx = fmaxf(v0, v1);
#pragma unroll
            for (int off = 16; off; off >>= 1)
                mx = fmaxf(mx, __shfl_xor_sync(0xFFFFFFFFu, mx, off));
            float mnew = fmaxf(m[i], mx);
            float sf = expf(m[i] - mnew);
            float p0 = expf(v0 - mnew);    // -inf -> 0
            float p1 = expf(v1 - mnew);
            float psum = p0 + p1;
#pragma unroll
            for (int off = 16; off; off >>= 1)
                psum += __shfl_xor_sync(0xFFFFFFFFu, psum, off);
            l[i] = l[i] * sf + psum;
            m[i] = mnew;
            o[i].x *= sf; o[i].y *= sf; o[i].z *= sf; o[i].w *= sf;
            Ps[(r0 + i) * PPITCH + c0] = p0;
            Ps[(r0 + i) * PPITCH + c1] = p1;
        }
        __syncwarp();

        // --- O += P @ V   (lane owns d = lane*4..+3)
#pragma unroll 4
        for (int k = 0; k < 64; ++k) {
            float4 v4 = *(const float4*)(Vs + k * QPITCH + lane * 4);
#pragma unroll
            for (int i = 0; i < 8; i++) {
                float p = Ps[(r0 + i) * PPITCH + k];
                o[i].x += p * v4.x; o[i].y += p * v4.y;
                o[i].z += p * v4.z; o[i].w += p * v4.w;
            }
        }
    }

    // --- epilogue: normalize + write ctx[b, q, h*128 + d]
#pragma unroll
    for (int i = 0; i < 8; i++) {
        float inv = 1.f / l[i];
        int qr = qt * 64 + r0 + i;
        float4 r = make_float4(o[i].x * inv, o[i].y * inv, o[i].z * inv, o[i].w * inv);
        *(float4*)(g_ctx + ((size_t)(b * SEQ + qr)) * HID + h * HD + lane * 4) = r;
    }
}

// ---------------- launch ----------------
extern "C" void kernel_launch(void* const* d_in, const int* in_sizes, int n_in,
                              void* d_out, int out_size)
{
    const float* x    = (const float*)d_in[0];   // [B,S,H]
    const float* qkvw = (const float*)d_in[1];   // [H, 3H]
    const float* dw   = (const float*)d_in[2];   // [H, H]
    const float* rel  = (const float*)d_in[3];   // [32, 16]
    float* out = (float*)d_out;

    float *p_qkv, *p_ctx;
    cudaGetSymbolAddress((void**)&p_qkv, g_qkv);
    cudaGetSymbolAddress((void**)&p_ctx, g_ctx);

    // 1) QKV GEMM: [4096,2048] @ [2048,6144]
    sgemm128<<<dim3(3 * HID / 128, BATCH * SEQ / 128), 256>>>(
        x, qkvw, p_qkv, BATCH * SEQ, 3 * HID, HID);

    // 2) RoPE + layout split
    rope_split_kernel<<<(BATCH * SEQ * NHEADS * 64) / 256, 256>>>();

    // 3) bias table
    bias_kernel<<<(NHEADS * SEQ + 255) / 256, 256>>>(rel);

    // 4) flash attention
    cudaFuncSetAttribute(flash_kernel, cudaFuncAttributeMaxDynamicSharedMemorySize,
                         FLASH_SMEM);
    flash_kernel<<<dim3(SEQ / 64, NHEADS, BATCH), 256, FLASH_SMEM>>>();

    // 5) dense GEMM: [4096,2048] @ [2048,2048]
    sgemm128<<<dim3(HID / 128, BATCH * SEQ / 128), 256>>>(
        p_ctx, dw, out, BATCH * SEQ, HID, HID);
}

// round 3
// speedup vs baseline: 1.2667x; 1.2667x over previous
#include <cuda_runtime.h>
#include <math.h>
#include <float.h>
#include <stdint.h>

#define BATCH   2
#define SEQ     2048
#define HID     2048
#define NHEADS  16
#define HD      128

// ---------------- static scratch (no allocations allowed) ----------------
__device__ float g_qkv  [BATCH * SEQ * 3 * HID];       // [B,S,3H]
__device__ float g_Q    [BATCH * NHEADS * SEQ * HD];   // [B,NH,S,D]
__device__ float g_K    [BATCH * NHEADS * SEQ * HD];
__device__ float g_V    [BATCH * NHEADS * SEQ * HD];
__device__ float g_ctx  [BATCH * SEQ * HID];           // [B,S,H]
__device__ float g_bias [NHEADS * SEQ];                // bias[h][q-k]

// ======================= helpers =======================
__device__ __forceinline__ uint32_t smem_u32(const void* p) {
    uint32_t a;
    asm("{ .reg .u64 t; cvta.to.shared.u64 t, %1; cvt.u32.u64 %0, t; }"
        : "=r"(a) : "l"(p));
    return a;
}
__device__ __forceinline__ uint32_t f2tf32(float x) {
    uint32_t r;
    asm("cvt.rna.tf32.f32 %0, %1;" : "=r"(r) : "f"(x));
    return r;
}
__device__ __forceinline__ void cp16(uint32_t s, const void* g) {
    asm volatile("cp.async.cg.shared.global [%0], [%1], 16;" :: "r"(s), "l"(g));
}
#define CP_COMMIT() asm volatile("cp.async.commit_group;" ::: "memory")
#define CP_WAIT1()  asm volatile("cp.async.wait_group 1;"  ::: "memory")

__device__ __forceinline__ void mma1688(float* d, const uint32_t* a, const uint32_t* b) {
    asm volatile(
        "mma.sync.aligned.m16n8k8.row.col.f32.tf32.tf32.f32 "
        "{%0,%1,%2,%3}, {%4,%5,%6,%7}, {%8,%9}, {%0,%1,%2,%3};"
        : "+f"(d[0]), "+f"(d[1]), "+f"(d[2]), "+f"(d[3])
        : "r"(a[0]), "r"(a[1]), "r"(a[2]), "r"(a[3]), "r"(b[0]), "r"(b[1]));
}

// ======================= tf32 mma.sync GEMM =======================
// C[M,N] = A[M,K] @ B[K,N]  (both row-major). 128x128 tile, BK=16, 3-stage cp.async.
#define GBM 128
#define GBN 128
#define GBK 16
#define APITCH 20                  // floats; 20*r mod 32 hits all residues -> conflict-free
#define BPITCH 136                 // floats; 136*q mod 32 = 8q -> conflict-free
#define A_STG (GBM * APITCH)       // 2560 floats
#define B_STG (GBK * BPITCH)       // 2176 floats
#define STG_FLOATS (A_STG + B_STG) // 4736 floats = 18944 B
#define GEMM_SMEM (3 * STG_FLOATS * 4)   // 56832 B

__global__ __launch_bounds__(256, 2) void gemm_mma(
    const float* __restrict__ A, const float* __restrict__ B,
    float* __restrict__ C, int M, int N, int K)
{
    extern __shared__ float sm[];
    const int tid  = threadIdx.x;
    const int warp = tid >> 5, lane = tid & 31;
    const int wm = (warp >> 2) * 64;       // warp row offset in tile
    const int wn = (warp & 3) * 32;        // warp col offset in tile
    const int r  = lane >> 2;              // groupID 0..7
    const int q  = lane & 3;               // threadID_in_group 0..3
    const int row0 = blockIdx.y * GBM;
    const int col0 = blockIdx.x * GBN;
    const uint32_t sb = smem_u32(sm);
    const int NC = K / GBK;

    float cf[4][4][4];
#pragma unroll
    for (int i = 0; i < 4; i++)
#pragma unroll
        for (int j = 0; j < 4; j++)
#pragma unroll
            for (int t = 0; t < 4; t++) cf[i][j][t] = 0.f;

    // per-thread load slots
    const int am  = tid >> 2;              // 0..63?  no: tid>>2 = 0..63 for j=tid; plus +64 for j=tid+256
    const int akq = (tid & 3) * 4;
    const int bk  = tid >> 5;              // 0..7 ; +8 for second
    const int bn4 = (tid & 31) * 4;

    auto load_stage = [&](int c, int s) {
        uint32_t base = sb + (uint32_t)(s * STG_FLOATS) * 4u;
        // A: 128 rows x 16 floats
        cp16(base + (uint32_t)((am      ) * APITCH + akq) * 4u,
             A + (size_t)(row0 + am      ) * K + c * GBK + akq);
        cp16(base + (uint32_t)((am + 64 ) * APITCH + akq) * 4u,
             A + (size_t)(row0 + am + 64 ) * K + c * GBK + akq);
        // B: 16 rows x 128 floats
        uint32_t bbase = base + (uint32_t)A_STG * 4u;
        cp16(bbase + (uint32_t)((bk    ) * BPITCH + bn4) * 4u,
             B + (size_t)(c * GBK + bk    ) * N + col0 + bn4);
        cp16(bbase + (uint32_t)((bk + 8) * BPITCH + bn4) * 4u,
             B + (size_t)(c * GBK + bk + 8) * N + col0 + bn4);
        CP_COMMIT();
    };

    load_stage(0, 0);
    load_stage(1, 1);

    int buf = 0;
    for (int c = 0; c < NC; ++c) {
        CP_WAIT1();
        __syncthreads();
        int nc = c + 2;
        if (nc < NC) load_stage(nc, nc % 3); else CP_COMMIT();

        const float* As = sm + buf * STG_FLOATS;
        const float* Bs = As + A_STG;
#pragma unroll
        for (int k8 = 0; k8 < GBK; k8 += 8) {
            uint32_t af[4][4], bf[4][2];
#pragma unroll
            for (int mt = 0; mt < 4; mt++) {
                int row = wm + mt * 16 + r;
                af[mt][0] = f2tf32(As[(row    ) * APITCH + k8 + q    ]);
                af[mt][1] = f2tf32(As[(row + 8) * APITCH + k8 + q    ]);
                af[mt][2] = f2tf32(As[(row    ) * APITCH + k8 + q + 4]);
                af[mt][3] = f2tf32(As[(row + 8) * APITCH + k8 + q + 4]);
            }
#pragma unroll
            for (int nt = 0; nt < 4; nt++) {
                int cc = wn + nt * 8 + r;
                bf[nt][0] = f2tf32(Bs[(k8 + q    ) * BPITCH + cc]);
                bf[nt][1] = f2tf32(Bs[(k8 + q + 4) * BPITCH + cc]);
            }
#pragma unroll
            for (int mt = 0; mt < 4; mt++)
#pragma unroll
                for (int nt = 0; nt < 4; nt++)
                    mma1688(cf[mt][nt], af[mt], bf[nt]);
        }
        buf = (buf + 1) % 3;
    }

    // epilogue
#pragma unroll
    for (int mt = 0; mt < 4; mt++) {
        int row = row0 + wm + mt * 16 + r;
#pragma unroll
        for (int nt = 0; nt < 4; nt++) {
            int col = col0 + wn + nt * 8 + 2 * q;
            *(float2*)(C + (size_t)row * N + col) =
                make_float2(cf[mt][nt][0], cf[mt][nt][1]);
            *(float2*)(C + (size_t)(row + 8) * N + col) =
                make_float2(cf[mt][nt][2], cf[mt][nt][3]);
        }
    }
}

// ---------------- RoPE + split to [B,NH,S,D] layout ----------------
__global__ __launch_bounds__(256) void rope_split_kernel()
{
    int t = blockIdx.x * blockDim.x + threadIdx.x;
    int d = t & 63;
    int h = (t >> 6) & (NHEADS - 1);
    int s = (t >> 10) & (SEQ - 1);
    int b = t >> 21;

    const float* base = g_qkv + ((size_t)(b * SEQ + s)) * (3 * HID) + h * HD;
    float q1 = base[d],            q2 = base[d + 64];
    float k1 = base[HID + d],      k2 = base[HID + d + 64];
    float v1 = base[2 * HID + d],  v2 = base[2 * HID + d + 64];

    float inv  = powf(10000.f, -(float)d * (1.f / 64.f));
    float ang  = (float)s * inv;
    float sn, cs;
    sincosf(ang, &sn, &cs);

    size_t o = ((size_t)((b * NHEADS + h) * SEQ + s)) * HD;
    g_Q[o + d]      = q1 * cs - q2 * sn;
    g_Q[o + d + 64] = q2 * cs + q1 * sn;
    g_K[o + d]      = k1 * cs - k2 * sn;
    g_K[o + d + 64] = k2 * cs + k1 * sn;
    g_V[o + d]      = v1;
    g_V[o + d + 64] = v2;
}

// ---------------- relative-position bias table ----------------
__global__ void bias_kernel(const float* __restrict__ rel)
{
    int idx = blockIdx.x * blockDim.x + threadIdx.x;
    if (idx >= NHEADS * SEQ) return;
    int h = idx >> 11;
    int n = idx & (SEQ - 1);
    int bucket;
    if (n < 16) {
        bucket = n;
    } else {
        float val = logf((float)n * (1.f / 16.f)) / logf(8.f) * 16.f;
        int bi = (int)val + 16;
        bucket = bi < 31 ? bi : 31;
    }
    g_bias[idx] = rel[bucket * NHEADS + h];
}

// ---------------- flash attention (fp32, causal, +bias) ----------------
#define QPITCH 132
#define PPITCH 66
#define FLASH_SMEM ((3 * 64 * QPITCH + 64 * PPITCH) * 4)

__global__ __launch_bounds__(256, 1) void flash_kernel()
{
    extern __shared__ float sm[];
    float* Qs = sm;
    float* Ks = Qs + 64 * QPITCH;
    float* Vs = Ks + 64 * QPITCH;
    float* Ps = Vs + 64 * QPITCH;

    const int qt  = blockIdx.x;
    const int h   = blockIdx.y;
    const int b   = blockIdx.z;
    const int tid = threadIdx.x;
    const int warp = tid >> 5, lane = tid & 31;

    const size_t headBase = (size_t)(b * NHEADS + h) * SEQ * HD;
    const float* Qg = g_Q + headBase + (size_t)qt * 64 * HD;

    for (int f = tid; f < 2048; f += 256) {
        int r = f >> 5, c4 = f & 31;
        *(float4*)(Qs + r * QPITCH + c4 * 4) = *(const float4*)(Qg + r * HD + c4 * 4);
    }

    const int r0 = warp * 8;
    const int c0 = lane * 2, c1 = c0 + 1;
    const float scale = 0.08838834764831845f;
    const float* biasH = g_bias + h * SEQ;

    float m[8], l[8];
    float4 o[8];
#pragma unroll
    for (int i = 0; i < 8; i++) {
        m[i] = -INFINITY; l[i] = 0.f;
        o[i] = make_float4(0.f, 0.f, 0.f, 0.f);
    }

    for (int kt = 0; kt <= qt; ++kt) {
        __syncthreads();
        const float* Kg = g_K + headBase + (size_t)kt * 64 * HD;
        const float* Vg = g_V + headBase + (size_t)kt * 64 * HD;
        for (int f = tid; f < 2048; f += 256) {
            int r = f >> 5, c4 = f & 31;
            *(float4*)(Ks + r * QPITCH + c4 * 4) = *(const float4*)(Kg + r * HD + c4 * 4);
            *(float4*)(Vs + r * QPITCH + c4 * 4) = *(const float4*)(Vg + r * HD + c4 * 4);
        }
        __syncthreads();

        float s0[8], s1[8];
#pragma unroll
        for (int i = 0; i < 8; i++) { s0[i] = 0.f; s1[i] = 0.f; }
        const float* K0 = Ks + c0 * QPITCH;
        const float* K1 = Ks + c1 * QPITCH;
#pragma unroll 8
        for (int d4 = 0; d4 < 32; ++d4) {
            float4 k0 = *(const float4*)(K0 + d4 * 4);
            float4 k1 = *(const float4*)(K1 + d4 * 4);
#pragma unroll
            for (int i = 0; i < 8; i++) {
                float4 qv = *(const float4*)(Qs + (r0 + i) * QPITCH + d4 * 4);
                s0[i] += qv.x * k0.x + qv.y * k0.y + qv.z * k0.z + qv.w * k0.w;
                s1[i] += qv.x * k1.x + qv.y * k1.y + qv.z * k1.z + qv.w * k1.w;
            }
        }

        const int kc0 = kt * 64 + c0;
        const int kc1 = kc0 + 1;
#pragma unroll
        for (int i = 0; i < 8; i++) {
            int qr = qt * 64 + r0 + i;
            float v0 = (kc0 <= qr) ? (s0[i] * scale + biasH[qr - kc0]) : -INFINITY;
            float v1 = (kc1 <= qr) ? (s1[i] * scale + biasH[qr - kc1]) : -INFINITY;
            float mx = fmaxf(v0, v1);
#pragma unroll
            for (int off = 16; off; off >>= 1)
                mx = fmaxf(mx, __shfl_xor_sync(0xFFFFFFFFu, mx, off));
            float mnew = fmaxf(m[i], mx);
            float sf = expf(m[i] - mnew);
            float p0 = expf(v0 - mnew);
            float p1 = expf(v1 - mnew);
            float psum = p0 + p1;
#pragma unroll
            for (int off = 16; off; off >>= 1)
                psum += __shfl_xor_sync(0xFFFFFFFFu, psum, off);
            l[i] = l[i] * sf + psum;
            m[i] = mnew;
            o[i].x *= sf; o[i].y *= sf; o[i].z *= sf; o[i].w *= sf;
            Ps[(r0 + i) * PPITCH + c0] = p0;
            Ps[(r0 + i) * PPITCH + c1] = p1;
        }
        __syncwarp();

#pragma unroll 4
        for (int k = 0; k < 64; ++k) {
            float4 v4 = *(const float4*)(Vs + k * QPITCH + lane * 4);
#pragma unroll
            for (int i = 0; i < 8; i++) {
                float p = Ps[(r0 + i) * PPITCH + k];
                o[i].x += p * v4.x; o[i].y += p * v4.y;
                o[i].z += p * v4.z; o[i].w += p * v4.w;
            }
        }
    }

#pragma unroll
    for (int i = 0; i < 8; i++) {
        float inv = 1.f / l[i];
        int qr = qt * 64 + r0 + i;
        float4 rr = make_float4(o[i].x * inv, o[i].y * inv, o[i].z * inv, o[i].w * inv);
        *(float4*)(g_ctx + ((size_t)(b * SEQ + qr)) * HID + h * HD + lane * 4) = rr;
    }
}

// ---------------- launch ----------------
extern "C" void kernel_launch(void* const* d_in, const int* in_sizes, int n_in,
                              void* d_out, int out_size)
{
    const float* x    = (const float*)d_in[0];   // [B,S,H]
    const float* qkvw = (const float*)d_in[1];   // [H, 3H]
    const float* dw   = (const float*)d_in[2];   // [H, H]
    const float* rel  = (const float*)d_in[3];   // [32, 16]
    float* out = (float*)d_out;

    float *p_qkv, *p_ctx;
    cudaGetSymbolAddress((void**)&p_qkv, g_qkv);
    cudaGetSymbolAddress((void**)&p_ctx, g_ctx);

    cudaFuncSetAttribute(gemm_mma, cudaFuncAttributeMaxDynamicSharedMemorySize, GEMM_SMEM);

    // 1) QKV GEMM (tf32 mma.sync): [4096,2048] @ [2048,6144]
    gemm_mma<<<dim3(3 * HID / GBN, BATCH * SEQ / GBM), 256, GEMM_SMEM>>>(
        x, qkvw, p_qkv, BATCH * SEQ, 3 * HID, HID);

    // 2) RoPE + layout split
    rope_split_kernel<<<(BATCH * SEQ * NHEADS * 64) / 256, 256>>>();

    // 3) bias table
    bias_kernel<<<(NHEADS * SEQ + 255) / 256, 256>>>(rel);

    // 4) flash attention (fp32)
    cudaFuncSetAttribute(flash_kernel, cudaFuncAttributeMaxDynamicSharedMemorySize, FLASH_SMEM);
    flash_kernel<<<dim3(SEQ / 64, NHEADS, BATCH), 256, FLASH_SMEM>>>();

    // 5) dense GEMM (tf32 mma.sync): [4096,2048] @ [2048,2048]
    gemm_mma<<<dim3(HID / GBN, BATCH * SEQ / GBM), 256, GEMM_SMEM>>>(
        p_ctx, dw, out, BATCH * SEQ, HID, HID);
}

// round 4
// speedup vs baseline: 2.7166x; 2.1446x over previous
#include <cuda_runtime.h>
#include <math.h>
#include <float.h>
#include <stdint.h>

#define BATCH   2
#define SEQ     2048
#define HID     2048
#define NHEADS  16
#define HD      128

// ---------------- static scratch (no allocations allowed) ----------------
__device__ float g_qkv  [BATCH * SEQ * 3 * HID];       // [B,S,3H]
__device__ float g_Q    [BATCH * NHEADS * SEQ * HD];   // [B,NH,S,D]
__device__ float g_K    [BATCH * NHEADS * SEQ * HD];
__device__ float g_V    [BATCH * NHEADS * SEQ * HD];
__device__ float g_ctx  [BATCH * SEQ * HID];           // [B,S,H]
__device__ float g_bias [NHEADS * SEQ];                // bias[h][q-k]

// ======================= helpers =======================
__device__ __forceinline__ uint32_t smem_u32(const void* p) {
    uint32_t a;
    asm("{ .reg .u64 t; cvta.to.shared.u64 t, %1; cvt.u32.u64 %0, t; }"
        : "=r"(a) : "l"(p));
    return a;
}
__device__ __forceinline__ uint32_t f2tf32(float x) {
    uint32_t r;
    asm("cvt.rna.tf32.f32 %0, %1;" : "=r"(r) : "f"(x));
    return r;
}
__device__ __forceinline__ void cp16(uint32_t s, const void* g) {
    asm volatile("cp.async.cg.shared.global [%0], [%1], 16;" :: "r"(s), "l"(g));
}
#define CP_COMMIT() asm volatile("cp.async.commit_group;" ::: "memory")
#define CP_WAIT1()  asm volatile("cp.async.wait_group 1;"  ::: "memory")
#define CP_WAIT0()  asm volatile("cp.async.wait_group 0;"  ::: "memory")

__device__ __forceinline__ void mma1688(float* d, const uint32_t* a, const uint32_t* b) {
    asm volatile(
        "mma.sync.aligned.m16n8k8.row.col.f32.tf32.tf32.f32 "
        "{%0,%1,%2,%3}, {%4,%5,%6,%7}, {%8,%9}, {%0,%1,%2,%3};"
        : "+f"(d[0]), "+f"(d[1]), "+f"(d[2]), "+f"(d[3])
        : "r"(a[0]), "r"(a[1]), "r"(a[2]), "r"(a[3]), "r"(b[0]), "r"(b[1]));
}

// ======================= tf32 mma.sync GEMM =======================
// C[M,N] = A[M,K] @ B[K,N]  (both row-major). 128x128 tile, BK=16, 3-stage cp.async.
#define GBM 128
#define GBN 128
#define GBK 16
#define APITCH 20
#define BPITCH 136
#define A_STG (GBM * APITCH)
#define B_STG (GBK * BPITCH)
#define STG_FLOATS (A_STG + B_STG)
#define GEMM_SMEM (3 * STG_FLOATS * 4)

__global__ __launch_bounds__(256, 2) void gemm_mma(
    const float* __restrict__ A, const float* __restrict__ B,
    float* __restrict__ C, int M, int N, int K)
{
    extern __shared__ float sm[];
    const int tid  = threadIdx.x;
    const int warp = tid >> 5, lane = tid & 31;
    const int wm = (warp >> 2) * 64;
    const int wn = (warp & 3) * 32;
    const int r  = lane >> 2;
    const int q  = lane & 3;
    const int row0 = blockIdx.y * GBM;
    const int col0 = blockIdx.x * GBN;
    const uint32_t sb = smem_u32(sm);
    const int NC = K / GBK;

    float cf[4][4][4];
#pragma unroll
    for (int i = 0; i < 4; i++)
#pragma unroll
        for (int j = 0; j < 4; j++)
#pragma unroll
            for (int t = 0; t < 4; t++) cf[i][j][t] = 0.f;

    const int am  = tid >> 2;
    const int akq = (tid & 3) * 4;
    const int bk  = tid >> 5;
    const int bn4 = (tid & 31) * 4;

    auto load_stage = [&](int c, int s) {
        uint32_t base = sb + (uint32_t)(s * STG_FLOATS) * 4u;
        cp16(base + (uint32_t)((am      ) * APITCH + akq) * 4u,
             A + (size_t)(row0 + am      ) * K + c * GBK + akq);
        cp16(base + (uint32_t)((am + 64 ) * APITCH + akq) * 4u,
             A + (size_t)(row0 + am + 64 ) * K + c * GBK + akq);
        uint32_t bbase = base + (uint32_t)A_STG * 4u;
        cp16(bbase + (uint32_t)((bk    ) * BPITCH + bn4) * 4u,
             B + (size_t)(c * GBK + bk    ) * N + col0 + bn4);
        cp16(bbase + (uint32_t)((bk + 8) * BPITCH + bn4) * 4u,
             B + (size_t)(c * GBK + bk + 8) * N + col0 + bn4);
        CP_COMMIT();
    };

    load_stage(0, 0);
    load_stage(1, 1);

    int buf = 0;
    for (int c = 0; c < NC; ++c) {
        CP_WAIT1();
        __syncthreads();
        int nc = c + 2;
        if (nc < NC) load_stage(nc, nc % 3); else CP_COMMIT();

        const float* As = sm + buf * STG_FLOATS;
        const float* Bs = As + A_STG;
#pragma unroll
        for (int k8 = 0; k8 < GBK; k8 += 8) {
            uint32_t af[4][4], bf[4][2];
#pragma unroll
            for (int mt = 0; mt < 4; mt++) {
                int row = wm + mt * 16 + r;
                af[mt][0] = f2tf32(As[(row    ) * APITCH + k8 + q    ]);
                af[mt][1] = f2tf32(As[(row + 8) * APITCH + k8 + q    ]);
                af[mt][2] = f2tf32(As[(row    ) * APITCH + k8 + q + 4]);
                af[mt][3] = f2tf32(As[(row + 8) * APITCH + k8 + q + 4]);
            }
#pragma unroll
            for (int nt = 0; nt < 4; nt++) {
                int cc = wn + nt * 8 + r;
                bf[nt][0] = f2tf32(Bs[(k8 + q    ) * BPITCH + cc]);
                bf[nt][1] = f2tf32(Bs[(k8 + q + 4) * BPITCH + cc]);
            }
#pragma unroll
            for (int mt = 0; mt < 4; mt++)
#pragma unroll
                for (int nt = 0; nt < 4; nt++)
                    mma1688(cf[mt][nt], af[mt], bf[nt]);
        }
        buf = (buf + 1) % 3;
    }

#pragma unroll
    for (int mt = 0; mt < 4; mt++) {
        int row = row0 + wm + mt * 16 + r;
#pragma unroll
        for (int nt = 0; nt < 4; nt++) {
            int col = col0 + wn + nt * 8 + 2 * q;
            *(float2*)(C + (size_t)row * N + col) =
                make_float2(cf[mt][nt][0], cf[mt][nt][1]);
            *(float2*)(C + (size_t)(row + 8) * N + col) =
                make_float2(cf[mt][nt][2], cf[mt][nt][3]);
        }
    }
}

// ---------------- RoPE + split to [B,NH,S,D] layout ----------------
__global__ __launch_bounds__(256) void rope_split_kernel()
{
    int t = blockIdx.x * blockDim.x + threadIdx.x;
    int d = t & 63;
    int h = (t >> 6) & (NHEADS - 1);
    int s = (t >> 10) & (SEQ - 1);
    int b = t >> 21;

    const float* base = g_qkv + ((size_t)(b * SEQ + s)) * (3 * HID) + h * HD;
    float q1 = base[d],            q2 = base[d + 64];
    float k1 = base[HID + d],      k2 = base[HID + d + 64];
    float v1 = base[2 * HID + d],  v2 = base[2 * HID + d + 64];

    float inv  = powf(10000.f, -(float)d * (1.f / 64.f));
    float ang  = (float)s * inv;
    float sn, cs;
    sincosf(ang, &sn, &cs);

    size_t o = ((size_t)((b * NHEADS + h) * SEQ + s)) * HD;
    g_Q[o + d]      = q1 * cs - q2 * sn;
    g_Q[o + d + 64] = q2 * cs + q1 * sn;
    g_K[o + d]      = k1 * cs - k2 * sn;
    g_K[o + d + 64] = k2 * cs + k1 * sn;
    g_V[o + d]      = v1;
    g_V[o + d + 64] = v2;
}

// ---------------- relative-position bias table ----------------
__global__ void bias_kernel(const float* __restrict__ rel)
{
    int idx = blockIdx.x * blockDim.x + threadIdx.x;
    if (idx >= NHEADS * SEQ) return;
    int h = idx >> 11;
    int n = idx & (SEQ - 1);
    int bucket;
    if (n < 16) {
        bucket = n;
    } else {
        float val = logf((float)n * (1.f / 16.f)) / logf(8.f) * 16.f;
        int bi = (int)val + 16;
        bucket = bi < 31 ? bi : 31;
    }
    g_bias[idx] = rel[bucket * NHEADS + h];
}

// ---------------- flash attention via tf32 mma.sync ----------------
// 64 q-rows x 64 k-cols per tile. 8 warps = 4(m16) x 2(half).
// smem pitches: Q/K 132 (a-frag pattern), V 136 (b-frag), P 68 (a-frag).
#define OFF_Q  0
#define OFF_K  8448                 // Ks[2][64*132]
#define OFF_V  (OFF_K + 2*8448)     // Vs[2][64*136]
#define OFF_P  (OFF_V + 2*8704)    // Ps[64*68]
#define OFF_BS (OFF_P + 4352)       // bs[128]
#define OFF_RM (OFF_BS + 128)       // redm[2][64]
#define OFF_RS (OFF_RM + 128)       // reds[2][64]
#define FLASH_FLOATS (OFF_RS + 128)
#define FLASH_SMEM (FLASH_FLOATS * 4)

__global__ __launch_bounds__(256, 1) void flash_mma_kernel()
{
    extern __shared__ float sm[];
    float* Qs   = sm + OFF_Q;
    float* Ks   = sm + OFF_K;
    float* Vs   = sm + OFF_V;
    float* Ps   = sm + OFF_P;
    float* bsm  = sm + OFF_BS;
    float* redm = sm + OFF_RM;
    float* reds = sm + OFF_RS;

    const int qt = blockIdx.x, h = blockIdx.y, b = blockIdx.z;
    const int tid  = threadIdx.x;
    const int warp = tid >> 5, lane = tid & 31;
    const int r = lane >> 2, q = lane & 3;
    const int warpm = warp >> 1, half = warp & 1;
    const uint32_t sbase = smem_u32(sm);

    const size_t headBase = (size_t)(b * NHEADS + h) * SEQ * HD;
    const float* Qg = g_Q + headBase + (size_t)qt * 64 * HD;
    const float* biasH = g_bias + h * SEQ;

    const float SCL2 = 0.08838834764831845f * 1.4426950408889634f;
    const float L2E  = 1.4426950408889634f;

    // ---- prolog: async load Q, then KV[0]
#pragma unroll
    for (int i = 0; i < 8; i++) {
        int f = tid + i * 256; int rr = f >> 5, c4 = (f & 31) * 4;
        cp16(sbase + (uint32_t)(OFF_Q + rr * 132 + c4) * 4u, Qg + rr * HD + c4);
    }
    CP_COMMIT();
    {
        const float* Kg = g_K + headBase + (size_t)qt * 0;  // kt=0
        const float* Vg = g_V + headBase;
        const float* K0 = g_K + headBase;
        (void)Kg;
#pragma unroll
        for (int i = 0; i < 8; i++) {
            int f = tid + i * 256; int rr = f >> 5, c4 = (f & 31) * 4;
            cp16(sbase + (uint32_t)(OFF_K + rr * 132 + c4) * 4u, K0 + rr * HD + c4);
            cp16(sbase + (uint32_t)(OFF_V + rr * 136 + c4) * 4u, Vg + rr * HD + c4);
        }
        CP_COMMIT();
    }
    CP_WAIT1();                    // Q done (KV0 still pending)
    __syncthreads();
    for (int j = tid; j < 8192; j += 256) {
        int rr = j >> 7, c = j & 127;
        Qs[rr * 132 + c] = __uint_as_float(f2tf32(Qs[rr * 132 + c]));
    }

    const int rA = warpm * 16 + r;      // local q-row A (0..63)
    const int rB = rA + 8;

    float m2[2] = { -1e30f, -1e30f };
    float lsum[2] = { 0.f, 0.f };
    float of[8][4];
#pragma unroll
    for (int nt = 0; nt < 8; nt++)
#pragma unroll
        for (int e = 0; e < 4; e++) of[nt][e] = 0.f;

    for (int kt = 0; kt <= qt; ++kt) {
        const int stage = kt & 1;
        float* Kst = Ks + stage * 8448;
        float* Vst = Vs + stage * 8704;

        __syncthreads();               // prev iter reads done (stages, Ps, red)
        if (kt < qt) {
            const int ns = (kt + 1) & 1;
            const float* Kg = g_K + headBase + (size_t)(kt + 1) * 64 * HD;
            const float* Vg = g_V + headBase + (size_t)(kt + 1) * 64 * HD;
#pragma unroll
            for (int i = 0; i < 8; i++) {
                int f = tid + i * 256; int rr = f >> 5, c4 = (f & 31) * 4;
                cp16(sbase + (uint32_t)(OFF_K + ns * 8448 + rr * 132 + c4) * 4u, Kg + rr * HD + c4);
                cp16(sbase + (uint32_t)(OFF_V + ns * 8704 + rr * 136 + c4) * 4u, Vg + rr * HD + c4);
            }
            CP_COMMIT();
            CP_WAIT1();                // KV[kt] complete
        } else {
            CP_WAIT0();
        }
        __syncthreads();               // cp.async data visible to all threads

        // in-place fp32 -> tf32 (RNA) for K and V; build bias diagonal table
        for (int j = tid; j < 8192; j += 256) {
            int rr = j >> 7, c = j & 127;
            Kst[rr * 132 + c] = __uint_as_float(f2tf32(Kst[rr * 132 + c]));
            Vst[rr * 136 + c] = __uint_as_float(f2tf32(Vst[rr * 136 + c]));
        }
        if (tid < 128) {
            int off = tid - 64 + (qt - kt) * 64;
            bsm[tid] = (off >= 0 ? biasH[off] : 0.f) * L2E;
        }
        __syncthreads();

        // ---- QK^T: S[16 x 32] per warp (cols half*32..+32)
        float s[4][4];
#pragma unroll
        for (int nt = 0; nt < 4; nt++)
#pragma unroll
            for (int e = 0; e < 4; e++) s[nt][e] = 0.f;

#pragma unroll
        for (int k8 = 0; k8 < 16; k8++) {
            int kc = k8 * 8;
            uint32_t af[4];
            af[0] = __float_as_uint(Qs[rA * 132 + kc + q]);
            af[1] = __float_as_uint(Qs[rB * 132 + kc + q]);
            af[2] = __float_as_uint(Qs[rA * 132 + kc + q + 4]);
            af[3] = __float_as_uint(Qs[rB * 132 + kc + q + 4]);
#pragma unroll
            for (int nt = 0; nt < 4; nt++) {
                int ck = half * 32 + nt * 8 + r;
                uint32_t bf[2];
                bf[0] = __float_as_uint(Kst[ck * 132 + kc + q]);
                bf[1] = __float_as_uint(Kst[ck * 132 + kc + q + 4]);
                mma1688(s[nt], af, bf);
            }
        }

        // ---- scale + bias + causal mask (exp2 domain)
        const bool diag = (kt == qt);
#pragma unroll
        for (int nt = 0; nt < 4; nt++) {
            int cb = half * 32 + nt * 8 + 2 * q;
            float b0a = bsm[rA - cb + 64], b1a = bsm[rA - cb + 63];
            float b0b = bsm[rB - cb + 64], b1b = bsm[rB - cb + 63];
            s[nt][0] = (diag && cb     > rA) ? -1e30f : s[nt][0] * SCL2 + b0a;
            s[nt][1] = (diag && cb + 1 > rA) ? -1e30f : s[nt][1] * SCL2 + b1a;
            s[nt][2] = (diag && cb     > rB) ? -1e30f : s[nt][2] * SCL2 + b0b;
            s[nt][3] = (diag && cb + 1 > rB) ? -1e30f : s[nt][3] * SCL2 + b1b;
        }

        // ---- row max (within warp: over own 8 cols + quad shuffle)
        float mxA = -1e30f, mxB = -1e30f;
#pragma unroll
        for (int nt = 0; nt < 4; nt++) {
            mxA = fmaxf(mxA, fmaxf(s[nt][0], s[nt][1]));
            mxB = fmaxf(mxB, fmaxf(s[nt][2], s[nt][3]));
        }
        mxA = fmaxf(mxA, __shfl_xor_sync(0xFFFFFFFFu, mxA, 1));
        mxA = fmaxf(mxA, __shfl_xor_sync(0xFFFFFFFFu, mxA, 2));
        mxB = fmaxf(mxB, __shfl_xor_sync(0xFFFFFFFFu, mxB, 1));
        mxB = fmaxf(mxB, __shfl_xor_sync(0xFFFFFFFFu, mxB, 2));
        if (q == 0) { redm[half * 64 + rA] = mxA; redm[half * 64 + rB] = mxB; }
        __syncthreads();
        float mA = fmaxf(redm[rA], redm[64 + rA]);
        float mB = fmaxf(redm[rB], redm[64 + rB]);
        float mnA = fmaxf(m2[0], mA), mnB = fmaxf(m2[1], mB);
        float corrA = exp2f(m2[0] - mnA), corrB = exp2f(m2[1] - mnB);
        m2[0] = mnA; m2[1] = mnB;

        // ---- P = exp2(s - m), store tf32 to smem, partial row sums
        float sA = 0.f, sB = 0.f;
#pragma unroll
        for (int nt = 0; nt < 4; nt++) {
            int cb = half * 32 + nt * 8 + 2 * q;
            float p0 = exp2f(s[nt][0] - mnA);
            float p1 = exp2f(s[nt][1] - mnA);
            float p2 = exp2f(s[nt][2] - mnB);
            float p3 = exp2f(s[nt][3] - mnB);
            sA += p0 + p1; sB += p2 + p3;
            *(float2*)(Ps + rA * 68 + cb) = make_float2(
                __uint_as_float(f2tf32(p0)), __uint_as_float(f2tf32(p1)));
            *(float2*)(Ps + rB * 68 + cb) = make_float2(
                __uint_as_float(f2tf32(p2)), __uint_as_float(f2tf32(p3)));
        }
        sA += __shfl_xor_sync(0xFFFFFFFFu, sA, 1);
        sA += __shfl_xor_sync(0xFFFFFFFFu, sA, 2);
        sB += __shfl_xor_sync(0xFFFFFFFFu, sB, 1);
        sB += __shfl_xor_sync(0xFFFFFFFFu, sB, 2);
        if (q == 0) { reds[half * 64 + rA] = sA; reds[half * 64 + rB] = sB; }

        // rescale O while P-store settles
#pragma unroll
        for (int nt = 0; nt < 8; nt++) {
            of[nt][0] *= corrA; of[nt][1] *= corrA;
            of[nt][2] *= corrB; of[nt][3] *= corrB;
        }
        __syncthreads();
        lsum[0] = lsum[0] * corrA + reds[rA] + reds[64 + rA];
        lsum[1] = lsum[1] * corrB + reds[rB] + reds[64 + rB];

        // ---- O += P @ V  (warp: rows m16, d-cols half*64..+64)
#pragma unroll
        for (int k8 = 0; k8 < 8; k8++) {
            int kc = k8 * 8;
            uint32_t pa[4];
            pa[0] = __float_as_uint(Ps[rA * 68 + kc + q]);
            pa[1] = __float_as_uint(Ps[rB * 68 + kc + q]);
            pa[2] = __float_as_uint(Ps[rA * 68 + kc + q + 4]);
            pa[3] = __float_as_uint(Ps[rB * 68 + kc + q + 4]);
#pragma unroll
            for (int nt = 0; nt < 8; nt++) {
                int dc = half * 64 + nt * 8 + r;
                uint32_t bf[2];
                bf[0] = __float_as_uint(Vst[(kc + q    ) * 136 + dc]);
                bf[1] = __float_as_uint(Vst[(kc + q + 4) * 136 + dc]);
                mma1688(of[nt], pa, bf);
            }
        }
    }

    // ---- epilogue: normalize, write ctx[b, q, h*128 + d]
    float liA = 1.f / lsum[0], liB = 1.f / lsum[1];
    int growA = qt * 64 + rA, growB = qt * 64 + rB;
#pragma unroll
    for (int nt = 0; nt < 8; nt++) {
        int col = h * HD + half * 64 + nt * 8 + 2 * q;
        *(float2*)(g_ctx + (size_t)(b * SEQ + growA) * HID + col) =
            make_float2(of[nt][0] * liA, of[nt][1] * liA);
        *(float2*)(g_ctx + (size_t)(b * SEQ + growB) * HID + col) =
            make_float2(of[nt][2] * liB, of[nt][3] * liB);
    }
}

// ---------------- launch ----------------
extern "C" void kernel_launch(void* const* d_in, const int* in_sizes, int n_in,
                              void* d_out, int out_size)
{
    const float* x    = (const float*)d_in[0];   // [B,S,H]
    const float* qkvw = (const float*)d_in[1];   // [H, 3H]
    const float* dw   = (const float*)d_in[2];   // [H, H]
    const float* rel  = (const float*)d_in[3];   // [32, 16]
    float* out = (float*)d_out;

    float *p_qkv, *p_ctx;
    cudaGetSymbolAddress((void**)&p_qkv, g_qkv);
    cudaGetSymbolAddress((void**)&p_ctx, g_ctx);

    cudaFuncSetAttribute(gemm_mma, cudaFuncAttributeMaxDynamicSharedMemorySize, GEMM_SMEM);
    cudaFuncSetAttribute(flash_mma_kernel, cudaFuncAttributeMaxDynamicSharedMemorySize, FLASH_SMEM);

    // 1) QKV GEMM (tf32 mma.sync): [4096,2048] @ [2048,6144]
    gemm_mma<<<dim3(3 * HID / GBN, BATCH * SEQ / GBM), 256, GEMM_SMEM>>>(
        x, qkvw, p_qkv, BATCH * SEQ, 3 * HID, HID);

    // 2) RoPE + layout split
    rope_split_kernel<<<(BATCH * SEQ * NHEADS * 64) / 256, 256>>>();

    // 3) bias table
    bias_kernel<<<(NHEADS * SEQ + 255) / 256, 256>>>(rel);

    // 4) flash attention (tf32 mma)
    flash_mma_kernel<<<dim3(SEQ / 64, NHEADS, BATCH), 256, FLASH_SMEM>>>();

    // 5) dense GEMM (tf32 mma.sync): [4096,2048] @ [2048,2048]
    gemm_mma<<<dim3(HID / GBN, BATCH * SEQ / GBM), 256, GEMM_SMEM>>>(
        p_ctx, dw, out, BATCH * SEQ, HID, HID);
}

// round 5
// speedup vs baseline: 3.2496x; 1.1962x over previous
#include <cuda_runtime.h>
#include <math.h>
#include <float.h>
#include <stdint.h>

#define BATCH   2
#define SEQ     2048
#define HID     2048
#define NHEADS  16
#define HD      128

// ---------------- static scratch (no allocations allowed) ----------------
__device__ float g_qkv  [BATCH * SEQ * 3 * HID];       // [B,S,3H]
__device__ float g_Q    [BATCH * NHEADS * SEQ * HD];   // [B,NH,S,D] (tf32-rounded)
__device__ float g_K    [BATCH * NHEADS * SEQ * HD];
__device__ float g_V    [BATCH * NHEADS * SEQ * HD];
__device__ float g_ctx  [BATCH * SEQ * HID];           // [B,S,H]
__device__ float g_bias [NHEADS * SEQ];                // bias[h][q-k]

// ======================= helpers =======================
__device__ __forceinline__ uint32_t smem_u32(const void* p) {
    uint32_t a;
    asm("{ .reg .u64 t; cvta.to.shared.u64 t, %1; cvt.u32.u64 %0, t; }"
        : "=r"(a) : "l"(p));
    return a;
}
__device__ __forceinline__ uint32_t f2tf32(float x) {
    uint32_t r;
    asm("cvt.rna.tf32.f32 %0, %1;" : "=r"(r) : "f"(x));
    return r;
}
__device__ __forceinline__ void cp16(uint32_t s, const void* g) {
    asm volatile("cp.async.cg.shared.global [%0], [%1], 16;" :: "r"(s), "l"(g));
}
#define CP_COMMIT() asm volatile("cp.async.commit_group;" ::: "memory")
#define CP_WAIT1()  asm volatile("cp.async.wait_group 1;"  ::: "memory")
#define CP_WAIT0()  asm volatile("cp.async.wait_group 0;"  ::: "memory")

__device__ __forceinline__ void mma1688(float* d, const uint32_t* a, const uint32_t* b) {
    asm volatile(
        "mma.sync.aligned.m16n8k8.row.col.f32.tf32.tf32.f32 "
        "{%0,%1,%2,%3}, {%4,%5,%6,%7}, {%8,%9}, {%0,%1,%2,%3};"
        : "+f"(d[0]), "+f"(d[1]), "+f"(d[2]), "+f"(d[3])
        : "r"(a[0]), "r"(a[1]), "r"(a[2]), "r"(a[3]), "r"(b[0]), "r"(b[1]));
}

// ======================= tf32 mma.sync GEMM (unchanged, passing) =======================
#define GBM 128
#define GBN 128
#define GBK 16
#define APITCH 20
#define BPITCH 136
#define A_STG (GBM * APITCH)
#define B_STG (GBK * BPITCH)
#define STG_FLOATS (A_STG + B_STG)
#define GEMM_SMEM (3 * STG_FLOATS * 4)

__global__ __launch_bounds__(256, 2) void gemm_mma(
    const float* __restrict__ A, const float* __restrict__ B,
    float* __restrict__ C, int M, int N, int K)
{
    extern __shared__ float sm[];
    const int tid  = threadIdx.x;
    const int warp = tid >> 5, lane = tid & 31;
    const int wm = (warp >> 2) * 64;
    const int wn = (warp & 3) * 32;
    const int r  = lane >> 2;
    const int q  = lane & 3;
    const int row0 = blockIdx.y * GBM;
    const int col0 = blockIdx.x * GBN;
    const uint32_t sb = smem_u32(sm);
    const int NC = K / GBK;

    float cf[4][4][4];
#pragma unroll
    for (int i = 0; i < 4; i++)
#pragma unroll
        for (int j = 0; j < 4; j++)
#pragma unroll
            for (int t = 0; t < 4; t++) cf[i][j][t] = 0.f;

    const int am  = tid >> 2;
    const int akq = (tid & 3) * 4;
    const int bk  = tid >> 5;
    const int bn4 = (tid & 31) * 4;

    auto load_stage = [&](int c, int s) {
        uint32_t base = sb + (uint32_t)(s * STG_FLOATS) * 4u;
        cp16(base + (uint32_t)((am      ) * APITCH + akq) * 4u,
             A + (size_t)(row0 + am      ) * K + c * GBK + akq);
        cp16(base + (uint32_t)((am + 64 ) * APITCH + akq) * 4u,
             A + (size_t)(row0 + am + 64 ) * K + c * GBK + akq);
        uint32_t bbase = base + (uint32_t)A_STG * 4u;
        cp16(bbase + (uint32_t)((bk    ) * BPITCH + bn4) * 4u,
             B + (size_t)(c * GBK + bk    ) * N + col0 + bn4);
        cp16(bbase + (uint32_t)((bk + 8) * BPITCH + bn4) * 4u,
             B + (size_t)(c * GBK + bk + 8) * N + col0 + bn4);
        CP_COMMIT();
    };

    load_stage(0, 0);
    load_stage(1, 1);

    int buf = 0;
    for (int c = 0; c < NC; ++c) {
        CP_WAIT1();
        __syncthreads();
        int nc = c + 2;
        if (nc < NC) load_stage(nc, nc % 3); else CP_COMMIT();

        const float* As = sm + buf * STG_FLOATS;
        const float* Bs = As + A_STG;
#pragma unroll
        for (int k8 = 0; k8 < GBK; k8 += 8) {
            uint32_t af[4][4], bf[4][2];
#pragma unroll
            for (int mt = 0; mt < 4; mt++) {
                int row = wm + mt * 16 + r;
                af[mt][0] = f2tf32(As[(row    ) * APITCH + k8 + q    ]);
                af[mt][1] = f2tf32(As[(row + 8) * APITCH + k8 + q    ]);
                af[mt][2] = f2tf32(As[(row    ) * APITCH + k8 + q + 4]);
                af[mt][3] = f2tf32(As[(row + 8) * APITCH + k8 + q + 4]);
            }
#pragma unroll
            for (int nt = 0; nt < 4; nt++) {
                int cc = wn + nt * 8 + r;
                bf[nt][0] = f2tf32(Bs[(k8 + q    ) * BPITCH + cc]);
                bf[nt][1] = f2tf32(Bs[(k8 + q + 4) * BPITCH + cc]);
            }
#pragma unroll
            for (int mt = 0; mt < 4; mt++)
#pragma unroll
                for (int nt = 0; nt < 4; nt++)
                    mma1688(cf[mt][nt], af[mt], bf[nt]);
        }
        buf = (buf + 1) % 3;
    }

#pragma unroll
    for (int mt = 0; mt < 4; mt++) {
        int row = row0 + wm + mt * 16 + r;
#pragma unroll
        for (int nt = 0; nt < 4; nt++) {
            int col = col0 + wn + nt * 8 + 2 * q;
            *(float2*)(C + (size_t)row * N + col) =
                make_float2(cf[mt][nt][0], cf[mt][nt][1]);
            *(float2*)(C + (size_t)(row + 8) * N + col) =
                make_float2(cf[mt][nt][2], cf[mt][nt][3]);
        }
    }
}

// ---------------- RoPE + split + tf32 pre-round ----------------
__global__ __launch_bounds__(256) void rope_split_kernel()
{
    int t = blockIdx.x * blockDim.x + threadIdx.x;
    int d = t & 63;
    int h = (t >> 6) & (NHEADS - 1);
    int s = (t >> 10) & (SEQ - 1);
    int b = t >> 21;

    const float* base = g_qkv + ((size_t)(b * SEQ + s)) * (3 * HID) + h * HD;
    float q1 = base[d],            q2 = base[d + 64];
    float k1 = base[HID + d],      k2 = base[HID + d + 64];
    float v1 = base[2 * HID + d],  v2 = base[2 * HID + d + 64];

    float inv  = powf(10000.f, -(float)d * (1.f / 64.f));
    float ang  = (float)s * inv;
    float sn, cs;
    sincosf(ang, &sn, &cs);

    size_t o = ((size_t)((b * NHEADS + h) * SEQ + s)) * HD;
    g_Q[o + d]      = __uint_as_float(f2tf32(q1 * cs - q2 * sn));
    g_Q[o + d + 64] = __uint_as_float(f2tf32(q2 * cs + q1 * sn));
    g_K[o + d]      = __uint_as_float(f2tf32(k1 * cs - k2 * sn));
    g_K[o + d + 64] = __uint_as_float(f2tf32(k2 * cs + k1 * sn));
    g_V[o + d]      = __uint_as_float(f2tf32(v1));
    g_V[o + d + 64] = __uint_as_float(f2tf32(v2));
}

// ---------------- relative-position bias table ----------------
__global__ void bias_kernel(const float* __restrict__ rel)
{
    int idx = blockIdx.x * blockDim.x + threadIdx.x;
    if (idx >= NHEADS * SEQ) return;
    int h = idx >> 11;
    int n = idx & (SEQ - 1);
    int bucket;
    if (n < 16) {
        bucket = n;
    } else {
        float val = logf((float)n * (1.f / 16.f)) / logf(8.f) * 16.f;
        int bi = (int)val + 16;
        bucket = bi < 31 ? bi : 31;
    }
    g_bias[idx] = rel[bucket * NHEADS + h];
}

// ---------------- flash attention, FA2-style tf32 mma ----------------
// 128 q-rows per block, 64 k-cols per iter. 8 warps; warp owns 16 full rows.
// P never leaves registers (quad shuffle transpose into a-fragments).
#define FQ   128
#define FKC  64
#define QP   132                       // a/b-frag pitch (132 % 32 == 4)
#define VP   136                       // V b-frag pitch (136 % 32 == 8)
#define OFF_FK (FQ * QP)               // 16896
#define OFF_FV (OFF_FK + 2 * FKC * QP) // 33792
#define OFF_FB (OFF_FV + 2 * FKC * VP) // 51200
#define FLASH_FLOATS (OFF_FB + 192)
#define FLASH_SMEM (FLASH_FLOATS * 4)  // 205568 B

__global__ __launch_bounds__(256, 1) void flash_mma_kernel()
{
    extern __shared__ float sm[];
    float* Qs  = sm;
    float* bsm = sm + OFF_FB;

    const int qt = (int)gridDim.x - 1 - (int)blockIdx.x;   // heavy blocks first
    const int h = blockIdx.y, b = blockIdx.z;
    const int tid  = threadIdx.x;
    const int warp = tid >> 5, lane = tid & 31;
    const int r = lane >> 2, q = lane & 3;
    const int wr0 = warp * 16;
    const int rA = wr0 + r, rB = rA + 8;
    const uint32_t sbase = smem_u32(sm);

    const size_t headBase = (size_t)(b * NHEADS + h) * SEQ * HD;
    const float* Qg = g_Q + headBase + (size_t)qt * FQ * HD;
    const float* biasH = g_bias + h * SEQ;

    const float SCL2 = 0.08838834764831845f * 1.4426950408889634f;
    const float L2E  = 1.4426950408889634f;

    // prolog: Q (group), then KV tile 0 (group)
#pragma unroll
    for (int i = 0; i < 16; i++) {
        int f = tid + i * 256; int rr = f >> 5, c4 = (f & 31) * 4;
        cp16(sbase + (uint32_t)(rr * QP + c4) * 4u, Qg + rr * HD + c4);
    }
    CP_COMMIT();
    {
        const float* Kg = g_K + headBase;
        const float* Vg = g_V + headBase;
#pragma unroll
        for (int i = 0; i < 8; i++) {
            int f = tid + i * 256; int rr = f >> 5, c4 = (f & 31) * 4;
            cp16(sbase + (uint32_t)(OFF_FK + rr * QP + c4) * 4u, Kg + rr * HD + c4);
            cp16(sbase + (uint32_t)(OFF_FV + rr * VP + c4) * 4u, Vg + rr * HD + c4);
        }
        CP_COMMIT();
    }

    float m0 = -1e30f, m1 = -1e30f, l0 = 0.f, l1 = 0.f;
    float of[16][4];
#pragma unroll
    for (int nt = 0; nt < 16; nt++)
#pragma unroll
        for (int e = 0; e < 4; e++) of[nt][e] = 0.f;

    const int NT = 2 * qt + 2;

    for (int kt = 0; kt < NT; ++kt) {
        __syncthreads();                 // all warps done with stage (kt+1)&1
        if (kt + 1 < NT) {
            const int ns = (kt + 1) & 1;
            const float* Kg = g_K + headBase + (size_t)(kt + 1) * FKC * HD;
            const float* Vg = g_V + headBase + (size_t)(kt + 1) * FKC * HD;
#pragma unroll
            for (int i = 0; i < 8; i++) {
                int f = tid + i * 256; int rr = f >> 5, c4 = (f & 31) * 4;
                cp16(sbase + (uint32_t)(OFF_FK + ns * FKC * QP + rr * QP + c4) * 4u, Kg + rr * HD + c4);
                cp16(sbase + (uint32_t)(OFF_FV + ns * FKC * VP + rr * VP + c4) * 4u, Vg + rr * HD + c4);
            }
            CP_COMMIT();
        }
        const int base = qt * FQ - kt * FKC;   // qr - kc offset
        if (tid < 192) {
            int dl = base + tid - 63;
            bsm[tid] = (dl >= 0) ? biasH[dl] * L2E : 0.f;
        }
        if (kt + 1 < NT) CP_WAIT1(); else CP_WAIT0();
        __syncthreads();                 // KV[kt] + bsm visible

        // fully-masked warp? (only the last diagonal tile, warps 0-3)
        if (base < -(wr0 + 15)) continue;

        const float* Kst = sm + OFF_FK + (kt & 1) * FKC * QP;
        const float* Vst = sm + OFF_FV + (kt & 1) * FKC * VP;

        // ---- S = Q K^T  (16 x 64 per warp)
        float s[8][4];
#pragma unroll
        for (int nt = 0; nt < 8; nt++)
#pragma unroll
            for (int e = 0; e < 4; e++) s[nt][e] = 0.f;

#pragma unroll
        for (int k8 = 0; k8 < 16; k8++) {
            int kc = k8 * 8;
            uint32_t af[4];
            af[0] = __float_as_uint(Qs[rA * QP + kc + q]);
            af[1] = __float_as_uint(Qs[rB * QP + kc + q]);
            af[2] = __float_as_uint(Qs[rA * QP + kc + q + 4]);
            af[3] = __float_as_uint(Qs[rB * QP + kc + q + 4]);
#pragma unroll
            for (int nt = 0; nt < 8; nt++) {
                uint32_t bf[2];
                bf[0] = __float_as_uint(Kst[(nt * 8 + r) * QP + kc + q]);
                bf[1] = __float_as_uint(Kst[(nt * 8 + r) * QP + kc + q + 4]);
                mma1688(s[nt], af, bf);
            }
        }

        // ---- scale + bias + causal mask (exp2 domain)
        const bool dg = (base < FQ);     // masking possible in this tile
#pragma unroll
        for (int nt = 0; nt < 8; nt++) {
            int lc = nt * 8 + 2 * q;
            float v0 = s[nt][0] * SCL2 + bsm[rA - lc + 63];
            float v1 = s[nt][1] * SCL2 + bsm[rA - lc + 62];
            float v2 = s[nt][2] * SCL2 + bsm[rB - lc + 63];
            float v3 = s[nt][3] * SCL2 + bsm[rB - lc + 62];
            s[nt][0] = (dg && lc     > rA + base) ? -1e30f : v0;
            s[nt][1] = (dg && lc + 1 > rA + base) ? -1e30f : v1;
            s[nt][2] = (dg && lc     > rB + base) ? -1e30f : v2;
            s[nt][3] = (dg && lc + 1 > rB + base) ? -1e30f : v3;
        }

        // ---- row max within quad
        float mxA = -1e30f, mxB = -1e30f;
#pragma unroll
        for (int nt = 0; nt < 8; nt++) {
            mxA = fmaxf(mxA, fmaxf(s[nt][0], s[nt][1]));
            mxB = fmaxf(mxB, fmaxf(s[nt][2], s[nt][3]));
        }
        mxA = fmaxf(mxA, __shfl_xor_sync(0xFFFFFFFFu, mxA, 1));
        mxA = fmaxf(mxA, __shfl_xor_sync(0xFFFFFFFFu, mxA, 2));
        mxB = fmaxf(mxB, __shfl_xor_sync(0xFFFFFFFFu, mxB, 1));
        mxB = fmaxf(mxB, __shfl_xor_sync(0xFFFFFFFFu, mxB, 2));
        float mn0 = fmaxf(m0, mxA), mn1 = fmaxf(m1, mxB);
        float c0 = exp2f(m0 - mn0), c1 = exp2f(m1 - mn1);
        m0 = mn0; m1 = mn1;

        // ---- P = exp2(s - m); partial sums; tf32-round in regs
        float sA = 0.f, sB = 0.f;
#pragma unroll
        for (int nt = 0; nt < 8; nt++) {
            float p0 = exp2f(s[nt][0] - mn0);
            float p1 = exp2f(s[nt][1] - mn0);
            float p2 = exp2f(s[nt][2] - mn1);
            float p3 = exp2f(s[nt][3] - mn1);
            sA += p0 + p1; sB += p2 + p3;
            s[nt][0] = __uint_as_float(f2tf32(p0));
            s[nt][1] = __uint_as_float(f2tf32(p1));
            s[nt][2] = __uint_as_float(f2tf32(p2));
            s[nt][3] = __uint_as_float(f2tf32(p3));
        }
        sA += __shfl_xor_sync(0xFFFFFFFFu, sA, 1);
        sA += __shfl_xor_sync(0xFFFFFFFFu, sA, 2);
        sB += __shfl_xor_sync(0xFFFFFFFFu, sB, 1);
        sB += __shfl_xor_sync(0xFFFFFFFFu, sB, 2);
        l0 = l0 * c0 + sA;
        l1 = l1 * c1 + sB;

        // ---- rescale O
#pragma unroll
        for (int nt = 0; nt < 16; nt++) {
            of[nt][0] *= c0; of[nt][1] *= c0;
            of[nt][2] *= c1; of[nt][3] *= c1;
        }

        // ---- O += P V : quad-shuffle P into a-frags, then 16 n-subtiles
        const int srcA = (lane & ~3) | (q >> 1);
        const int srcB = srcA | 2;
        const bool odd = q & 1;
#pragma unroll
        for (int g = 0; g < 8; g++) {
            float a0A = __shfl_sync(0xFFFFFFFFu, s[g][0], srcA);
            float a1A = __shfl_sync(0xFFFFFFFFu, s[g][1], srcA);
            float b0A = __shfl_sync(0xFFFFFFFFu, s[g][2], srcA);
            float b1A = __shfl_sync(0xFFFFFFFFu, s[g][3], srcA);
            float a0B = __shfl_sync(0xFFFFFFFFu, s[g][0], srcB);
            float a1B = __shfl_sync(0xFFFFFFFFu, s[g][1], srcB);
            float b0B = __shfl_sync(0xFFFFFFFFu, s[g][2], srcB);
            float b1B = __shfl_sync(0xFFFFFFFFu, s[g][3], srcB);
            uint32_t pa[4];
            pa[0] = __float_as_uint(odd ? a1A : a0A);   // P[rA][8g+q]
            pa[1] = __float_as_uint(odd ? b1A : b0A);   // P[rB][8g+q]
            pa[2] = __float_as_uint(odd ? a1B : a0B);   // P[rA][8g+q+4]
            pa[3] = __float_as_uint(odd ? b1B : b0B);   // P[rB][8g+q+4]
            int k0 = g * 8 + q, k1 = g * 8 + q + 4;
#pragma unroll
            for (int nt = 0; nt < 16; nt++) {
                int dc = nt * 8 + r;
                uint32_t bf[2];
                bf[0] = __float_as_uint(Vst[k0 * VP + dc]);
                bf[1] = __float_as_uint(Vst[k1 * VP + dc]);
                mma1688(of[nt], pa, bf);
            }
        }
    }

    // ---- epilogue
    float li0 = 1.f / l0, li1 = 1.f / l1;
    int growA = qt * FQ + rA, growB = qt * FQ + rB;
#pragma unroll
    for (int nt = 0; nt < 16; nt++) {
        int col = h * HD + nt * 8 + 2 * q;
        *(float2*)(g_ctx + (size_t)(b * SEQ + growA) * HID + col) =
            make_float2(of[nt][0] * li0, of[nt][1] * li0);
        *(float2*)(g_ctx + (size_t)(b * SEQ + growB) * HID + col) =
            make_float2(of[nt][2] * li1, of[nt][3] * li1);
    }
}

// ---------------- launch ----------------
extern "C" void kernel_launch(void* const* d_in, const int* in_sizes, int n_in,
                              void* d_out, int out_size)
{
    const float* x    = (const float*)d_in[0];   // [B,S,H]
    const float* qkvw = (const float*)d_in[1];   // [H, 3H]
    const float* dw   = (const float*)d_in[2];   // [H, H]
    const float* rel  = (const float*)d_in[3];   // [32, 16]
    float* out = (float*)d_out;

    float *p_qkv, *p_ctx;
    cudaGetSymbolAddress((void**)&p_qkv, g_qkv);
    cudaGetSymbolAddress((void**)&p_ctx, g_ctx);

    cudaFuncSetAttribute(gemm_mma, cudaFuncAttributeMaxDynamicSharedMemorySize, GEMM_SMEM);
    cudaFuncSetAttribute(flash_mma_kernel, cudaFuncAttributeMaxDynamicSharedMemorySize, FLASH_SMEM);

    // 1) QKV GEMM (tf32 mma.sync)
    gemm_mma<<<dim3(3 * HID / GBN, BATCH * SEQ / GBM), 256, GEMM_SMEM>>>(
        x, qkvw, p_qkv, BATCH * SEQ, 3 * HID, HID);

    // 2) RoPE + layout split + tf32 pre-round
    rope_split_kernel<<<(BATCH * SEQ * NHEADS * 64) / 256, 256>>>();

    // 3) bias table
    bias_kernel<<<(NHEADS * SEQ + 255) / 256, 256>>>(rel);

    // 4) flash attention (FA2-style tf32 mma)
    flash_mma_kernel<<<dim3(SEQ / FQ, NHEADS, BATCH), 256, FLASH_SMEM>>>();

    // 5) dense GEMM (tf32 mma.sync)
    gemm_mma<<<dim3(HID / GBN, BATCH * SEQ / GBM), 256, GEMM_SMEM>>>(
        p_ctx, dw, out, BATCH * SEQ, HID, HID);
}

// round 6
// speedup vs baseline: 3.5204x; 1.0833x over previous
#include <cuda_runtime.h>
#include <math.h>
#include <float.h>
#include <stdint.h>

#define BATCH   2
#define SEQ     2048
#define HID     2048
#define NHEADS  16
#define HD      128

// ---------------- static scratch (no allocations allowed) ----------------
__device__ float g_qkv  [BATCH * SEQ * 3 * HID];       // [B,S,3H]
__device__ float g_Q    [BATCH * NHEADS * SEQ * HD];   // [B,NH,S,D] (tf32-rounded)
__device__ float g_K    [BATCH * NHEADS * SEQ * HD];
__device__ float g_V    [BATCH * NHEADS * SEQ * HD];
__device__ float g_ctx  [BATCH * SEQ * HID];           // [B,S,H] (tf32-rounded)
__device__ float g_bias [NHEADS * SEQ];                // bias[h][q-k]
__device__ float g_xr   [BATCH * SEQ * HID];           // tf32-rounded x
__device__ float g_wqkvr[HID * 3 * HID];               // tf32-rounded qkv_w
__device__ float g_dwr  [HID * HID];                   // tf32-rounded dense_w
__device__ float g_cos  [SEQ * 64];                    // RoPE tables
__device__ float g_sin  [SEQ * 64];

// ======================= helpers =======================
__device__ __forceinline__ uint32_t smem_u32(const void* p) {
    uint32_t a;
    asm("{ .reg .u64 t; cvta.to.shared.u64 t, %1; cvt.u32.u64 %0, t; }"
        : "=r"(a) : "l"(p));
    return a;
}
__device__ __forceinline__ uint32_t f2tf32(float x) {
    uint32_t r;
    asm("cvt.rna.tf32.f32 %0, %1;" : "=r"(r) : "f"(x));
    return r;
}
__device__ __forceinline__ void cp16(uint32_t s, const void* g) {
    asm volatile("cp.async.cg.shared.global [%0], [%1], 16;" :: "r"(s), "l"(g));
}
#define CP_COMMIT() asm volatile("cp.async.commit_group;" ::: "memory")
#define CP_WAIT1()  asm volatile("cp.async.wait_group 1;"  ::: "memory")
#define CP_WAIT0()  asm volatile("cp.async.wait_group 0;"  ::: "memory")

__device__ __forceinline__ void mma1688(float* d, const uint32_t* a, const uint32_t* b) {
    asm volatile(
        "mma.sync.aligned.m16n8k8.row.col.f32.tf32.tf32.f32 "
        "{%0,%1,%2,%3}, {%4,%5,%6,%7}, {%8,%9}, {%0,%1,%2,%3};"
        : "+f"(d[0]), "+f"(d[1]), "+f"(d[2]), "+f"(d[3])
        : "r"(a[0]), "r"(a[1]), "r"(a[2]), "r"(a[3]), "r"(b[0]), "r"(b[1]));
}

// ======================= tf32 pre-round (elementwise, float4) =======================
__global__ __launch_bounds__(256) void tf32_round_kernel(
    const float* __restrict__ in, float* __restrict__ out)
{
    int i = blockIdx.x * blockDim.x + threadIdx.x;
    float4 v = ((const float4*)in)[i];
    v.x = __uint_as_float(f2tf32(v.x));
    v.y = __uint_as_float(f2tf32(v.y));
    v.z = __uint_as_float(f2tf32(v.z));
    v.w = __uint_as_float(f2tf32(v.w));
    ((float4*)out)[i] = v;
}

// ======================= RoPE cos/sin table =======================
__global__ __launch_bounds__(256) void rope_table_kernel()
{
    int idx = blockIdx.x * blockDim.x + threadIdx.x;   // SEQ*64
    int s = idx >> 6, d = idx & 63;
    float inv = powf(10000.f, -(float)d * (1.f / 64.f));
    float sn, cs;
    sincosf((float)s * inv, &sn, &cs);
    g_cos[idx] = cs;
    g_sin[idx] = sn;
}

// ======================= tf32 mma.sync GEMM (pre-rounded operands) =======================
#define GBM 128
#define GBN 128
#define GBK 16
#define APITCH 20
#define BPITCH 136
#define A_STG (GBM * APITCH)
#define B_STG (GBK * BPITCH)
#define STG_FLOATS (A_STG + B_STG)
#define GEMM_SMEM (3 * STG_FLOATS * 4)

__global__ __launch_bounds__(256, 2) void gemm_mma(
    const float* __restrict__ A, const float* __restrict__ B,
    float* __restrict__ C, int M, int N, int K)
{
    extern __shared__ float sm[];
    const int tid  = threadIdx.x;
    const int warp = tid >> 5, lane = tid & 31;
    const int wm = (warp >> 2) * 64;
    const int wn = (warp & 3) * 32;
    const int r  = lane >> 2;
    const int q  = lane & 3;
    const int row0 = blockIdx.y * GBM;
    const int col0 = blockIdx.x * GBN;
    const uint32_t sb = smem_u32(sm);
    const int NC = K / GBK;

    float cf[4][4][4];
#pragma unroll
    for (int i = 0; i < 4; i++)
#pragma unroll
        for (int j = 0; j < 4; j++)
#pragma unroll
            for (int t = 0; t < 4; t++) cf[i][j][t] = 0.f;

    const int am  = tid >> 2;
    const int akq = (tid & 3) * 4;
    const int bk  = tid >> 5;
    const int bn4 = (tid & 31) * 4;

    auto load_stage = [&](int c, int s) {
        uint32_t base = sb + (uint32_t)(s * STG_FLOATS) * 4u;
        cp16(base + (uint32_t)((am      ) * APITCH + akq) * 4u,
             A + (size_t)(row0 + am      ) * K + c * GBK + akq);
        cp16(base + (uint32_t)((am + 64 ) * APITCH + akq) * 4u,
             A + (size_t)(row0 + am + 64 ) * K + c * GBK + akq);
        uint32_t bbase = base + (uint32_t)A_STG * 4u;
        cp16(bbase + (uint32_t)((bk    ) * BPITCH + bn4) * 4u,
             B + (size_t)(c * GBK + bk    ) * N + col0 + bn4);
        cp16(bbase + (uint32_t)((bk + 8) * BPITCH + bn4) * 4u,
             B + (size_t)(c * GBK + bk + 8) * N + col0 + bn4);
        CP_COMMIT();
    };

    load_stage(0, 0);
    load_stage(1, 1);

    int buf = 0;
    for (int c = 0; c < NC; ++c) {
        CP_WAIT1();
        __syncthreads();
        int nc = c + 2;
        if (nc < NC) load_stage(nc, nc % 3); else CP_COMMIT();

        const float* As = sm + buf * STG_FLOATS;
        const float* Bs = As + A_STG;
#pragma unroll
        for (int k8 = 0; k8 < GBK; k8 += 8) {
            uint32_t af[4][4], bf[4][2];
#pragma unroll
            for (int mt = 0; mt < 4; mt++) {
                int row = wm + mt * 16 + r;
                af[mt][0] = __float_as_uint(As[(row    ) * APITCH + k8 + q    ]);
                af[mt][1] = __float_as_uint(As[(row + 8) * APITCH + k8 + q    ]);
                af[mt][2] = __float_as_uint(As[(row    ) * APITCH + k8 + q + 4]);
                af[mt][3] = __float_as_uint(As[(row + 8) * APITCH + k8 + q + 4]);
            }
#pragma unroll
            for (int nt = 0; nt < 4; nt++) {
                int cc = wn + nt * 8 + r;
                bf[nt][0] = __float_as_uint(Bs[(k8 + q    ) * BPITCH + cc]);
                bf[nt][1] = __float_as_uint(Bs[(k8 + q + 4) * BPITCH + cc]);
            }
#pragma unroll
            for (int mt = 0; mt < 4; mt++)
#pragma unroll
                for (int nt = 0; nt < 4; nt++)
                    mma1688(cf[mt][nt], af[mt], bf[nt]);
        }
        buf = (buf + 1) % 3;
    }

#pragma unroll
    for (int mt = 0; mt < 4; mt++) {
        int row = row0 + wm + mt * 16 + r;
#pragma unroll
        for (int nt = 0; nt < 4; nt++) {
            int col = col0 + wn + nt * 8 + 2 * q;
            *(float2*)(C + (size_t)row * N + col) =
                make_float2(cf[mt][nt][0], cf[mt][nt][1]);
            *(float2*)(C + (size_t)(row + 8) * N + col) =
                make_float2(cf[mt][nt][2], cf[mt][nt][3]);
        }
    }
}

// ---------------- RoPE + split + tf32 pre-round (table-driven) ----------------
__global__ __launch_bounds__(256) void rope_split_kernel()
{
    int t = blockIdx.x * blockDim.x + threadIdx.x;
    int d = t & 63;
    int h = (t >> 6) & (NHEADS - 1);
    int s = (t >> 10) & (SEQ - 1);
    int b = t >> 21;

    const float* base = g_qkv + ((size_t)(b * SEQ + s)) * (3 * HID) + h * HD;
    float q1 = base[d],            q2 = base[d + 64];
    float k1 = base[HID + d],      k2 = base[HID + d + 64];
    float v1 = base[2 * HID + d],  v2 = base[2 * HID + d + 64];

    float cs = g_cos[s * 64 + d];
    float sn = g_sin[s * 64 + d];

    size_t o = ((size_t)((b * NHEADS + h) * SEQ + s)) * HD;
    g_Q[o + d]      = __uint_as_float(f2tf32(q1 * cs - q2 * sn));
    g_Q[o + d + 64] = __uint_as_float(f2tf32(q2 * cs + q1 * sn));
    g_K[o + d]      = __uint_as_float(f2tf32(k1 * cs - k2 * sn));
    g_K[o + d + 64] = __uint_as_float(f2tf32(k2 * cs + k1 * sn));
    g_V[o + d]      = __uint_as_float(f2tf32(v1));
    g_V[o + d + 64] = __uint_as_float(f2tf32(v2));
}

// ---------------- relative-position bias table ----------------
__global__ void bias_kernel(const float* __restrict__ rel)
{
    int idx = blockIdx.x * blockDim.x + threadIdx.x;
    if (idx >= NHEADS * SEQ) return;
    int h = idx >> 11;
    int n = idx & (SEQ - 1);
    int bucket;
    if (n < 16) {
        bucket = n;
    } else {
        float val = logf((float)n * (1.f / 16.f)) / logf(8.f) * 16.f;
        int bi = (int)val + 16;
        bucket = bi < 31 ? bi : 31;
    }
    g_bias[idx] = rel[bucket * NHEADS + h];
}

// ---------------- flash attention, FA2-style tf32 mma ----------------
#define FQ   128
#define FKC  64
#define QP   132
#define VP   136
#define OFF_FK (FQ * QP)
#define OFF_FV (OFF_FK + 2 * FKC * QP)
#define OFF_FB (OFF_FV + 2 * FKC * VP)
#define FLASH_FLOATS (OFF_FB + 192)
#define FLASH_SMEM (FLASH_FLOATS * 4)

__global__ __launch_bounds__(256, 1) void flash_mma_kernel()
{
    extern __shared__ float sm[];
    float* Qs  = sm;
    float* bsm = sm + OFF_FB;

    const int qt = (int)gridDim.x - 1 - (int)blockIdx.x;   // heavy blocks first
    const int h = blockIdx.y, b = blockIdx.z;
    const int tid  = threadIdx.x;
    const int warp = tid >> 5, lane = tid & 31;
    const int r = lane >> 2, q = lane & 3;
    const int wr0 = warp * 16;
    const int rA = wr0 + r, rB = rA + 8;
    const uint32_t sbase = smem_u32(sm);

    const size_t headBase = (size_t)(b * NHEADS + h) * SEQ * HD;
    const float* Qg = g_Q + headBase + (size_t)qt * FQ * HD;
    const float* biasH = g_bias + h * SEQ;

    const float SCL2 = 0.08838834764831845f * 1.4426950408889634f;
    const float L2E  = 1.4426950408889634f;

#pragma unroll
    for (int i = 0; i < 16; i++) {
        int f = tid + i * 256; int rr = f >> 5, c4 = (f & 31) * 4;
        cp16(sbase + (uint32_t)(rr * QP + c4) * 4u, Qg + rr * HD + c4);
    }
    CP_COMMIT();
    {
        const float* Kg = g_K + headBase;
        const float* Vg = g_V + headBase;
#pragma unroll
        for (int i = 0; i < 8; i++) {
            int f = tid + i * 256; int rr = f >> 5, c4 = (f & 31) * 4;
            cp16(sbase + (uint32_t)(OFF_FK + rr * QP + c4) * 4u, Kg + rr * HD + c4);
            cp16(sbase + (uint32_t)(OFF_FV + rr * VP + c4) * 4u, Vg + rr * HD + c4);
        }
        CP_COMMIT();
    }

    float m0 = -1e30f, m1 = -1e30f, l0 = 0.f, l1 = 0.f;
    float of[16][4];
#pragma unroll
    for (int nt = 0; nt < 16; nt++)
#pragma unroll
        for (int e = 0; e < 4; e++) of[nt][e] = 0.f;

    const int NT = 2 * qt + 2;

    for (int kt = 0; kt < NT; ++kt) {
        __syncthreads();
        if (kt + 1 < NT) {
            const int ns = (kt + 1) & 1;
            const float* Kg = g_K + headBase + (size_t)(kt + 1) * FKC * HD;
            const float* Vg = g_V + headBase + (size_t)(kt + 1) * FKC * HD;
#pragma unroll
            for (int i = 0; i < 8; i++) {
                int f = tid + i * 256; int rr = f >> 5, c4 = (f & 31) * 4;
                cp16(sbase + (uint32_t)(OFF_FK + ns * FKC * QP + rr * QP + c4) * 4u, Kg + rr * HD + c4);
                cp16(sbase + (uint32_t)(OFF_FV + ns * FKC * VP + rr * VP + c4) * 4u, Vg + rr * HD + c4);
            }
            CP_COMMIT();
        }
        const int base = qt * FQ - kt * FKC;
        if (tid < 192) {
            int dl = base + tid - 63;
            bsm[tid] = (dl >= 0) ? biasH[dl] * L2E : 0.f;
        }
        if (kt + 1 < NT) CP_WAIT1(); else CP_WAIT0();
        __syncthreads();

        if (base < -(wr0 + 15)) continue;

        const float* Kst = sm + OFF_FK + (kt & 1) * FKC * QP;
        const float* Vst = sm + OFF_FV + (kt & 1) * FKC * VP;

        float s[8][4];
#pragma unroll
        for (int nt = 0; nt < 8; nt++)
#pragma unroll
            for (int e = 0; e < 4; e++) s[nt][e] = 0.f;

#pragma unroll
        for (int k8 = 0; k8 < 16; k8++) {
            int kc = k8 * 8;
            uint32_t af[4];
            af[0] = __float_as_uint(Qs[rA * QP + kc + q]);
            af[1] = __float_as_uint(Qs[rB * QP + kc + q]);
            af[2] = __float_as_uint(Qs[rA * QP + kc + q + 4]);
            af[3] = __float_as_uint(Qs[rB * QP + kc + q + 4]);
#pragma unroll
            for (int nt = 0; nt < 8; nt++) {
                uint32_t bf[2];
                bf[0] = __float_as_uint(Kst[(nt * 8 + r) * QP + kc + q]);
                bf[1] = __float_as_uint(Kst[(nt * 8 + r) * QP + kc + q + 4]);
                mma1688(s[nt], af, bf);
            }
        }

        const bool dg = (base < FQ);
#pragma unroll
        for (int nt = 0; nt < 8; nt++) {
            int lc = nt * 8 + 2 * q;
            float v0 = s[nt][0] * SCL2 + bsm[rA - lc + 63];
            float v1 = s[nt][1] * SCL2 + bsm[rA - lc + 62];
            float v2 = s[nt][2] * SCL2 + bsm[rB - lc + 63];
            float v3 = s[nt][3] * SCL2 + bsm[rB - lc + 62];
            s[nt][0] = (dg && lc     > rA + base) ? -1e30f : v0;
            s[nt][1] = (dg && lc + 1 > rA + base) ? -1e30f : v1;
            s[nt][2] = (dg && lc     > rB + base) ? -1e30f : v2;
            s[nt][3] = (dg && lc + 1 > rB + base) ? -1e30f : v3;
        }

        float mxA = -1e30f, mxB = -1e30f;
#pragma unroll
        for (int nt = 0; nt < 8; nt++) {
            mxA = fmaxf(mxA, fmaxf(s[nt][0], s[nt][1]));
            mxB = fmaxf(mxB, fmaxf(s[nt][2], s[nt][3]));
        }
        mxA = fmaxf(mxA, __shfl_xor_sync(0xFFFFFFFFu, mxA, 1));
        mxA = fmaxf(mxA, __shfl_xor_sync(0xFFFFFFFFu, mxA, 2));
        mxB = fmaxf(mxB, __shfl_xor_sync(0xFFFFFFFFu, mxB, 1));
        mxB = fmaxf(mxB, __shfl_xor_sync(0xFFFFFFFFu, mxB, 2));
        float mn0 = fmaxf(m0, mxA), mn1 = fmaxf(m1, mxB);
        float c0 = exp2f(m0 - mn0), c1 = exp2f(m1 - mn1);
        m0 = mn0; m1 = mn1;

        float sA = 0.f, sB = 0.f;
#pragma unroll
        for (int nt = 0; nt < 8; nt++) {
            float p0 = exp2f(s[nt][0] - mn0);
            float p1 = exp2f(s[nt][1] - mn0);
            float p2 = exp2f(s[nt][2] - mn1);
            float p3 = exp2f(s[nt][3] - mn1);
            sA += p0 + p1; sB += p2 + p3;
            s[nt][0] = __uint_as_float(f2tf32(p0));
            s[nt][1] = __uint_as_float(f2tf32(p1));
            s[nt][2] = __uint_as_float(f2tf32(p2));
            s[nt][3] = __uint_as_float(f2tf32(p3));
        }
        sA += __shfl_xor_sync(0xFFFFFFFFu, sA, 1);
        sA += __shfl_xor_sync(0xFFFFFFFFu, sA, 2);
        sB += __shfl_xor_sync(0xFFFFFFFFu, sB, 1);
        sB += __shfl_xor_sync(0xFFFFFFFFu, sB, 2);
        l0 = l0 * c0 + sA;
        l1 = l1 * c1 + sB;

#pragma unroll
        for (int nt = 0; nt < 16; nt++) {
            of[nt][0] *= c0; of[nt][1] *= c0;
            of[nt][2] *= c1; of[nt][3] *= c1;
        }

        const int srcA = (lane & ~3) | (q >> 1);
        const int srcB = srcA | 2;
        const bool odd = q & 1;
#pragma unroll
        for (int g = 0; g < 8; g++) {
            float a0A = __shfl_sync(0xFFFFFFFFu, s[g][0], srcA);
            float a1A = __shfl_sync(0xFFFFFFFFu, s[g][1], srcA);
            float b0A = __shfl_sync(0xFFFFFFFFu, s[g][2], srcA);
            float b1A = __shfl_sync(0xFFFFFFFFu, s[g][3], srcA);
            float a0B = __shfl_sync(0xFFFFFFFFu, s[g][0], srcB);
            float a1B = __shfl_sync(0xFFFFFFFFu, s[g][1], srcB);
            float b0B = __shfl_sync(0xFFFFFFFFu, s[g][2], srcB);
            float b1B = __shfl_sync(0xFFFFFFFFu, s[g][3], srcB);
            uint32_t pa[4];
            pa[0] = __float_as_uint(odd ? a1A : a0A);
            pa[1] = __float_as_uint(odd ? b1A : b0A);
            pa[2] = __float_as_uint(odd ? a1B : a0B);
            pa[3] = __float_as_uint(odd ? b1B : b0B);
            int k0 = g * 8 + q, k1 = g * 8 + q + 4;
#pragma unroll
            for (int nt = 0; nt < 16; nt++) {
                int dc = nt * 8 + r;
                uint32_t bf[2];
                bf[0] = __float_as_uint(Vst[k0 * VP + dc]);
                bf[1] = __float_as_uint(Vst[k1 * VP + dc]);
                mma1688(of[nt], pa, bf);
            }
        }
    }

    // epilogue: normalize + tf32-round (dense GEMM consumes rounded anyway)
    float li0 = 1.f / l0, li1 = 1.f / l1;
    int growA = qt * FQ + rA, growB = qt * FQ + rB;
#pragma unroll
    for (int nt = 0; nt < 16; nt++) {
        int col = h * HD + nt * 8 + 2 * q;
        *(float2*)(g_ctx + (size_t)(b * SEQ + growA) * HID + col) = make_float2(
            __uint_as_float(f2tf32(of[nt][0] * li0)),
            __uint_as_float(f2tf32(of[nt][1] * li0)));
        *(float2*)(g_ctx + (size_t)(b * SEQ + growB) * HID + col) = make_float2(
            __uint_as_float(f2tf32(of[nt][2] * li1)),
            __uint_as_float(f2tf32(of[nt][3] * li1)));
    }
}

// ---------------- launch ----------------
extern "C" void kernel_launch(void* const* d_in, const int* in_sizes, int n_in,
                              void* d_out, int out_size)
{
    const float* x    = (const float*)d_in[0];   // [B,S,H]
    const float* qkvw = (const float*)d_in[1];   // [H, 3H]
    const float* dw   = (const float*)d_in[2];   // [H, H]
    const float* rel  = (const float*)d_in[3];   // [32, 16]
    float* out = (float*)d_out;

    float *p_qkv, *p_ctx, *p_xr, *p_wqkvr, *p_dwr;
    cudaGetSymbolAddress((void**)&p_qkv,   g_qkv);
    cudaGetSymbolAddress((void**)&p_ctx,   g_ctx);
    cudaGetSymbolAddress((void**)&p_xr,    g_xr);
    cudaGetSymbolAddress((void**)&p_wqkvr, g_wqkvr);
    cudaGetSymbolAddress((void**)&p_dwr,   g_dwr);

    cudaFuncSetAttribute(gemm_mma, cudaFuncAttributeMaxDynamicSharedMemorySize, GEMM_SMEM);
    cudaFuncSetAttribute(flash_mma_kernel, cudaFuncAttributeMaxDynamicSharedMemorySize, FLASH_SMEM);

    // 0) pre-round operands to tf32; RoPE tables
    tf32_round_kernel<<<(BATCH * SEQ * HID / 4) / 256, 256>>>(x, p_xr);
    tf32_round_kernel<<<(HID * 3 * HID / 4) / 256, 256>>>(qkvw, p_wqkvr);
    tf32_round_kernel<<<(HID * HID / 4) / 256, 256>>>(dw, p_dwr);
    rope_table_kernel<<<(SEQ * 64) / 256, 256>>>();

    // 1) QKV GEMM (tf32 mma.sync, pre-rounded)
    gemm_mma<<<dim3(3 * HID / GBN, BATCH * SEQ / GBM), 256, GEMM_SMEM>>>(
        p_xr, p_wqkvr, p_qkv, BATCH * SEQ, 3 * HID, HID);

    // 2) RoPE + layout split + tf32 pre-round
    rope_split_kernel<<<(BATCH * SEQ * NHEADS * 64) / 256, 256>>>();

    // 3) bias table
    bias_kernel<<<(NHEADS * SEQ + 255) / 256, 256>>>(rel);

    // 4) flash attention (FA2-style tf32 mma)
    flash_mma_kernel<<<dim3(SEQ / FQ, NHEADS, BATCH), 256, FLASH_SMEM>>>();

    // 5) dense GEMM (tf32 mma.sync, pre-rounded ctx/dw)
    gemm_mma<<<dim3(HID / GBN, BATCH * SEQ / GBM), 256, GEMM_SMEM>>>(
        p_ctx, p_dwr, out, BATCH * SEQ, HID, HID);
}

// round 7
// speedup vs baseline: 3.5381x; 1.0050x over previous
#include <cuda_runtime.h>
#include <math.h>
#include <float.h>
#include <stdint.h>

#define BATCH   2
#define SEQ     2048
#define HID     2048
#define NHEADS  16
#define HD      128

// ---------------- static scratch (no allocations allowed) ----------------
__device__ float g_qkv  [BATCH * SEQ * 3 * HID];       // [B,S,3H]
__device__ float g_Q    [BATCH * NHEADS * SEQ * HD];   // [B,NH,S,D] (tf32-rounded)
__device__ float g_K    [BATCH * NHEADS * SEQ * HD];
__device__ float g_V    [BATCH * NHEADS * SEQ * HD];
__device__ float g_ctx  [BATCH * SEQ * HID];           // [B,S,H] (tf32-rounded)
__device__ float g_bias [NHEADS * SEQ];                // bias[h][q-k]
__device__ float g_xr   [BATCH * SEQ * HID];           // tf32-rounded x
__device__ float g_wqkvr[HID * 3 * HID];               // tf32-rounded qkv_w
__device__ float g_dwr  [HID * HID];                   // tf32-rounded dense_w
__device__ float g_cos  [SEQ * 64];                    // RoPE tables
__device__ float g_sin  [SEQ * 64];

// ======================= helpers =======================
__device__ __forceinline__ uint32_t smem_u32(const void* p) {
    uint32_t a;
    asm("{ .reg .u64 t; cvta.to.shared.u64 t, %1; cvt.u32.u64 %0, t; }"
        : "=r"(a) : "l"(p));
    return a;
}
__device__ __forceinline__ uint32_t f2tf32(float x) {
    uint32_t r;
    asm("cvt.rna.tf32.f32 %0, %1;" : "=r"(r) : "f"(x));
    return r;
}
__device__ __forceinline__ void cp16(uint32_t s, const void* g) {
    asm volatile("cp.async.cg.shared.global [%0], [%1], 16;" :: "r"(s), "l"(g));
}
__device__ __forceinline__ void cp4(uint32_t s, const void* g) {
    asm volatile("cp.async.ca.shared.global [%0], [%1], 4;" :: "r"(s), "l"(g));
}
#define CP_COMMIT() asm volatile("cp.async.commit_group;" ::: "memory")
#define CP_WAIT1()  asm volatile("cp.async.wait_group 1;"  ::: "memory")
#define CP_WAIT0()  asm volatile("cp.async.wait_group 0;"  ::: "memory")

__device__ __forceinline__ void mma1688(float* d, const uint32_t* a, const uint32_t* b) {
    asm volatile(
        "mma.sync.aligned.m16n8k8.row.col.f32.tf32.tf32.f32 "
        "{%0,%1,%2,%3}, {%4,%5,%6,%7}, {%8,%9}, {%0,%1,%2,%3};"
        : "+f"(d[0]), "+f"(d[1]), "+f"(d[2]), "+f"(d[3])
        : "r"(a[0]), "r"(a[1]), "r"(a[2]), "r"(a[3]), "r"(b[0]), "r"(b[1]));
}

// ======================= tf32 pre-round (elementwise, float4) =======================
__global__ __launch_bounds__(256) void tf32_round_kernel(
    const float* __restrict__ in, float* __restrict__ out)
{
    int i = blockIdx.x * blockDim.x + threadIdx.x;
    float4 v = ((const float4*)in)[i];
    v.x = __uint_as_float(f2tf32(v.x));
    v.y = __uint_as_float(f2tf32(v.y));
    v.z = __uint_as_float(f2tf32(v.z));
    v.w = __uint_as_float(f2tf32(v.w));
    ((float4*)out)[i] = v;
}

// ======================= RoPE cos/sin table =======================
__global__ __launch_bounds__(256) void rope_table_kernel()
{
    int idx = blockIdx.x * blockDim.x + threadIdx.x;   // SEQ*64
    int s = idx >> 6, d = idx & 63;
    float inv = powf(10000.f, -(float)d * (1.f / 64.f));
    float sn, cs;
    sincosf((float)s * inv, &sn, &cs);
    g_cos[idx] = cs;
    g_sin[idx] = sn;
}

// ======================= tf32 mma.sync GEMM: 128x256 tile, warp 64x64 ==============
#define GBM 128
#define GBN 256
#define GBK 16
#define APITCH 20                  // 20r mod 32 distinct -> conflict-free a-frags
#define BPITCH 264                 // 264q mod 32 = 8q    -> conflict-free b-frags
#define A_STG (GBM * APITCH)       // 2560 floats
#define B_STG (GBK * BPITCH)       // 4224 floats
#define STG_FLOATS (A_STG + B_STG) // 6784 floats
#define GEMM_SMEM (3 * STG_FLOATS * 4)   // 81408 B

__global__ __launch_bounds__(256, 1) void gemm_mma(
    const float* __restrict__ A, const float* __restrict__ B,
    float* __restrict__ C, int M, int N, int K)
{
    extern __shared__ float sm[];
    const int tid  = threadIdx.x;
    const int warp = tid >> 5, lane = tid & 31;
    const int wm = (warp >> 2) * 64;       // 0 or 64
    const int wn = (warp & 3) * 64;        // 0..192
    const int r  = lane >> 2;
    const int q  = lane & 3;
    const int row0 = blockIdx.y * GBM;
    const int col0 = blockIdx.x * GBN;
    const uint32_t sb = smem_u32(sm);
    const int NC = K / GBK;

    float cf[4][8][4];
#pragma unroll
    for (int i = 0; i < 4; i++)
#pragma unroll
        for (int j = 0; j < 8; j++)
#pragma unroll
            for (int t = 0; t < 4; t++) cf[i][j][t] = 0.f;

    const int am  = tid >> 2;              // 0..63 (A rows, two waves of 64)
    const int akq = (tid & 3) * 4;
    const int bkr = tid >> 6;              // 0..3  (B rows, 4 waves of 4)
    const int bn4 = (tid & 63) * 4;        // 0..252

    auto load_stage = [&](int c, int s) {
        uint32_t base = sb + (uint32_t)(s * STG_FLOATS) * 4u;
        cp16(base + (uint32_t)((am      ) * APITCH + akq) * 4u,
             A + (size_t)(row0 + am      ) * K + c * GBK + akq);
        cp16(base + (uint32_t)((am + 64 ) * APITCH + akq) * 4u,
             A + (size_t)(row0 + am + 64 ) * K + c * GBK + akq);
        uint32_t bbase = base + (uint32_t)A_STG * 4u;
#pragma unroll
        for (int j = 0; j < 4; j++) {
            cp16(bbase + (uint32_t)((bkr + 4 * j) * BPITCH + bn4) * 4u,
                 B + (size_t)(c * GBK + bkr + 4 * j) * N + col0 + bn4);
        }
        CP_COMMIT();
    };

    load_stage(0, 0);
    load_stage(1, 1);

    int buf = 0;
    for (int c = 0; c < NC; ++c) {
        CP_WAIT1();
        __syncthreads();
        int nc = c + 2;
        if (nc < NC) load_stage(nc, nc % 3); else CP_COMMIT();

        const float* As = sm + buf * STG_FLOATS;
        const float* Bs = As + A_STG;
#pragma unroll
        for (int k8 = 0; k8 < GBK; k8 += 8) {
            uint32_t af[4][4], bf[8][2];
#pragma unroll
            for (int mt = 0; mt < 4; mt++) {
                int row = wm + mt * 16 + r;
                af[mt][0] = __float_as_uint(As[(row    ) * APITCH + k8 + q    ]);
                af[mt][1] = __float_as_uint(As[(row + 8) * APITCH + k8 + q    ]);
                af[mt][2] = __float_as_uint(As[(row    ) * APITCH + k8 + q + 4]);
                af[mt][3] = __float_as_uint(As[(row + 8) * APITCH + k8 + q + 4]);
            }
#pragma unroll
            for (int nt = 0; nt < 8; nt++) {
                int cc = wn + nt * 8 + r;
                bf[nt][0] = __float_as_uint(Bs[(k8 + q    ) * BPITCH + cc]);
                bf[nt][1] = __float_as_uint(Bs[(k8 + q + 4) * BPITCH + cc]);
            }
#pragma unroll
            for (int mt = 0; mt < 4; mt++)
#pragma unroll
                for (int nt = 0; nt < 8; nt++)
                    mma1688(cf[mt][nt], af[mt], bf[nt]);
        }
        buf = (buf + 1) % 3;
    }

#pragma unroll
    for (int mt = 0; mt < 4; mt++) {
        int row = row0 + wm + mt * 16 + r;
#pragma unroll
        for (int nt = 0; nt < 8; nt++) {
            int col = col0 + wn + nt * 8 + 2 * q;
            *(float2*)(C + (size_t)row * N + col) =
                make_float2(cf[mt][nt][0], cf[mt][nt][1]);
            *(float2*)(C + (size_t)(row + 8) * N + col) =
                make_float2(cf[mt][nt][2], cf[mt][nt][3]);
        }
    }
}

// ---------------- RoPE + split + tf32 pre-round (table-driven) ----------------
__global__ __launch_bounds__(256) void rope_split_kernel()
{
    int t = blockIdx.x * blockDim.x + threadIdx.x;
    int d = t & 63;
    int h = (t >> 6) & (NHEADS - 1);
    int s = (t >> 10) & (SEQ - 1);
    int b = t >> 21;

    const float* base = g_qkv + ((size_t)(b * SEQ + s)) * (3 * HID) + h * HD;
    float q1 = base[d],            q2 = base[d + 64];
    float k1 = base[HID + d],      k2 = base[HID + d + 64];
    float v1 = base[2 * HID + d],  v2 = base[2 * HID + d + 64];

    float cs = g_cos[s * 64 + d];
    float sn = g_sin[s * 64 + d];

    size_t o = ((size_t)((b * NHEADS + h) * SEQ + s)) * HD;
    g_Q[o + d]      = __uint_as_float(f2tf32(q1 * cs - q2 * sn));
    g_Q[o + d + 64] = __uint_as_float(f2tf32(q2 * cs + q1 * sn));
    g_K[o + d]      = __uint_as_float(f2tf32(k1 * cs - k2 * sn));
    g_K[o + d + 64] = __uint_as_float(f2tf32(k2 * cs + k1 * sn));
    g_V[o + d]      = __uint_as_float(f2tf32(v1));
    g_V[o + d + 64] = __uint_as_float(f2tf32(v2));
}

// ---------------- relative-position bias table ----------------
__global__ void bias_kernel(const float* __restrict__ rel)
{
    int idx = blockIdx.x * blockDim.x + threadIdx.x;
    if (idx >= NHEADS * SEQ) return;
    int h = idx >> 11;
    int n = idx & (SEQ - 1);
    int bucket;
    if (n < 16) {
        bucket = n;
    } else {
        float val = logf((float)n * (1.f / 16.f)) / logf(8.f) * 16.f;
        int bi = (int)val + 16;
        bucket = bi < 31 ? bi : 31;
    }
    g_bias[idx] = rel[bucket * NHEADS + h];
}

// ---------------- flash attention, FA2-style tf32 mma ----------------
// 128 q-rows per block, 64 k-cols per iter. Q fragments hoisted to registers.
// Bias diagonal double-buffered and prefetched via cp.async with K/V.
#define FQ   128
#define FKC  64
#define QP   132
#define VP   136
#define OFF_FK (FQ * QP)
#define OFF_FV (OFF_FK + 2 * FKC * QP)
#define OFF_FB (OFF_FV + 2 * FKC * VP)
#define FLASH_FLOATS (OFF_FB + 2 * 192)
#define FLASH_SMEM (FLASH_FLOATS * 4)

__global__ __launch_bounds__(256, 1) void flash_mma_kernel()
{
    extern __shared__ float sm[];
    float* Qs = sm;

    const int qt = (int)gridDim.x - 1 - (int)blockIdx.x;   // heavy blocks first
    const int h = blockIdx.y, b = blockIdx.z;
    const int tid  = threadIdx.x;
    const int warp = tid >> 5, lane = tid & 31;
    const int r = lane >> 2, q = lane & 3;
    const int wr0 = warp * 16;
    const int rA = wr0 + r, rB = rA + 8;
    const uint32_t sbase = smem_u32(sm);

    const size_t headBase = (size_t)(b * NHEADS + h) * SEQ * HD;
    const float* Qg = g_Q + headBase + (size_t)qt * FQ * HD;
    const float* biasH = g_bias + h * SEQ;

    const float SCL2 = 0.08838834764831845f * 1.4426950408889634f;
    const float L2E  = 1.4426950408889634f;

    // prolog: Q (group0), then KV tile 0 + bias0 (group1)
#pragma unroll
    for (int i = 0; i < 16; i++) {
        int f = tid + i * 256; int rr = f >> 5, c4 = (f & 31) * 4;
        cp16(sbase + (uint32_t)(rr * QP + c4) * 4u, Qg + rr * HD + c4);
    }
    CP_COMMIT();
    {
        const float* Kg = g_K + headBase;
        const float* Vg = g_V + headBase;
#pragma unroll
        for (int i = 0; i < 8; i++) {
            int f = tid + i * 256; int rr = f >> 5, c4 = (f & 31) * 4;
            cp16(sbase + (uint32_t)(OFF_FK + rr * QP + c4) * 4u, Kg + rr * HD + c4);
            cp16(sbase + (uint32_t)(OFF_FV + rr * VP + c4) * 4u, Vg + rr * HD + c4);
        }
        if (tid < 192) {
            int dl = qt * FQ + tid - 63;
            cp4(sbase + (uint32_t)(OFF_FB + tid) * 4u, biasH + (dl >= 0 ? dl : 0));
        }
        CP_COMMIT();
    }
    CP_WAIT1();                        // Q done
    __syncthreads();

    // hoist Q fragments to registers (loop-invariant)
    uint32_t qf[16][4];
#pragma unroll
    for (int k8 = 0; k8 < 16; k8++) {
        int kc = k8 * 8;
        qf[k8][0] = __float_as_uint(Qs[rA * QP + kc + q]);
        qf[k8][1] = __float_as_uint(Qs[rB * QP + kc + q]);
        qf[k8][2] = __float_as_uint(Qs[rA * QP + kc + q + 4]);
        qf[k8][3] = __float_as_uint(Qs[rB * QP + kc + q + 4]);
    }

    float m0 = -1e30f, m1 = -1e30f, l0 = 0.f, l1 = 0.f;
    float of[16][4];
#pragma unroll
    for (int nt = 0; nt < 16; nt++)
#pragma unroll
        for (int e = 0; e < 4; e++) of[nt][e] = 0.f;

    const int NT = 2 * qt + 2;

    for (int kt = 0; kt < NT; ++kt) {
        __syncthreads();               // all warps done reading stage (kt+1)&1 & its bias
        if (kt + 1 < NT) {
            const int ns = (kt + 1) & 1;
            const float* Kg = g_K + headBase + (size_t)(kt + 1) * FKC * HD;
            const float* Vg = g_V + headBase + (size_t)(kt + 1) * FKC * HD;
#pragma unroll
            for (int i = 0; i < 8; i++) {
                int f = tid + i * 256; int rr = f >> 5, c4 = (f & 31) * 4;
                cp16(sbase + (uint32_t)(OFF_FK + ns * FKC * QP + rr * QP + c4) * 4u, Kg + rr * HD + c4);
                cp16(sbase + (uint32_t)(OFF_FV + ns * FKC * VP + rr * VP + c4) * 4u, Vg + rr * HD + c4);
            }
            if (tid < 192) {
                int dl = qt * FQ - (kt + 1) * FKC + tid - 63;
                cp4(sbase + (uint32_t)(OFF_FB + ns * 192 + tid) * 4u,
                    biasH + (dl >= 0 ? dl : 0));
            }
            CP_COMMIT();
            CP_WAIT1();                // KV[kt] + bias[kt] complete
        } else {
            CP_WAIT0();
        }
        __syncthreads();

        const int base = qt * FQ - kt * FKC;
        if (base < -(wr0 + 15)) continue;       // fully-masked warp

        const float* Kst = sm + OFF_FK + (kt & 1) * FKC * QP;
        const float* Vst = sm + OFF_FV + (kt & 1) * FKC * VP;
        const float* bsm = sm + OFF_FB + (kt & 1) * 192;

        // ---- S = Q K^T (16 x 64 per warp)
        float s[8][4];
#pragma unroll
        for (int nt = 0; nt < 8; nt++)
#pragma unroll
            for (int e = 0; e < 4; e++) s[nt][e] = 0.f;

#pragma unroll
        for (int k8 = 0; k8 < 16; k8++) {
            int kc = k8 * 8;
#pragma unroll
            for (int nt = 0; nt < 8; nt++) {
                uint32_t bf[2];
                bf[0] = __float_as_uint(Kst[(nt * 8 + r) * QP + kc + q]);
                bf[1] = __float_as_uint(Kst[(nt * 8 + r) * QP + kc + q + 4]);
                mma1688(s[nt], qf[k8], bf);
            }
        }

        // ---- scale + bias + causal mask (exp2 domain); bias pre-scaled? no: *L2E here
        const bool dg = (base < FQ);
#pragma unroll
        for (int nt = 0; nt < 8; nt++) {
            int lc = nt * 8 + 2 * q;
            float v0 = s[nt][0] * SCL2 + bsm[rA - lc + 63] * L2E;
            float v1 = s[nt][1] * SCL2 + bsm[rA - lc + 62] * L2E;
            float v2 = s[nt][2] * SCL2 + bsm[rB - lc + 63] * L2E;
            float v3 = s[nt][3] * SCL2 + bsm[rB - lc + 62] * L2E;
            s[nt][0] = (dg && lc     > rA + base) ? -1e30f : v0;
            s[nt][1] = (dg && lc + 1 > rA + base) ? -1e30f : v1;
            s[nt][2] = (dg && lc     > rB + base) ? -1e30f : v2;
            s[nt][3] = (dg && lc + 1 > rB + base) ? -1e30f : v3;
        }

        // ---- row max within quad
        float mxA = -1e30f, mxB = -1e30f;
#pragma unroll
        for (int nt = 0; nt < 8; nt++) {
            mxA = fmaxf(mxA, fmaxf(s[nt][0], s[nt][1]));
            mxB = fmaxf(mxB, fmaxf(s[nt][2], s[nt][3]));
        }
        mxA = fmaxf(mxA, __shfl_xor_sync(0xFFFFFFFFu, mxA, 1));
        mxA = fmaxf(mxA, __shfl_xor_sync(0xFFFFFFFFu, mxA, 2));
        mxB = fmaxf(mxB, __shfl_xor_sync(0xFFFFFFFFu, mxB, 1));
        mxB = fmaxf(mxB, __shfl_xor_sync(0xFFFFFFFFu, mxB, 2));
        float mn0 = fmaxf(m0, mxA), mn1 = fmaxf(m1, mxB);
        float c0 = exp2f(m0 - mn0), c1 = exp2f(m1 - mn1);
        m0 = mn0; m1 = mn1;

        // ---- P = exp2(s - m); partial sums; tf32-round in regs
        float sA = 0.f, sB = 0.f;
#pragma unroll
        for (int nt = 0; nt < 8; nt++) {
            float p0 = exp2f(s[nt][0] - mn0);
            float p1 = exp2f(s[nt][1] - mn0);
            float p2 = exp2f(s[nt][2] - mn1);
            float p3 = exp2f(s[nt][3] - mn1);
            sA += p0 + p1; sB += p2 + p3;
            s[nt][0] = __uint_as_float(f2tf32(p0));
            s[nt][1] = __uint_as_float(f2tf32(p1));
            s[nt][2] = __uint_as_float(f2tf32(p2));
            s[nt][3] = __uint_as_float(f2tf32(p3));
        }
        sA += __shfl_xor_sync(0xFFFFFFFFu, sA, 1);
        sA += __shfl_xor_sync(0xFFFFFFFFu, sA, 2);
        sB += __shfl_xor_sync(0xFFFFFFFFu, sB, 1);
        sB += __shfl_xor_sync(0xFFFFFFFFu, sB, 2);
        l0 = l0 * c0 + sA;
        l1 = l1 * c1 + sB;

#pragma unroll
        for (int nt = 0; nt < 16; nt++) {
            of[nt][0] *= c0; of[nt][1] *= c0;
            of[nt][2] *= c1; of[nt][3] *= c1;
        }

        // ---- O += P V : quad-shuffle P into a-frags
        const int srcA = (lane & ~3) | (q >> 1);
        const int srcB = srcA | 2;
        const bool odd = q & 1;
#pragma unroll
        for (int g = 0; g < 8; g++) {
            float a0A = __shfl_sync(0xFFFFFFFFu, s[g][0], srcA);
            float a1A = __shfl_sync(0xFFFFFFFFu, s[g][1], srcA);
            float b0A = __shfl_sync(0xFFFFFFFFu, s[g][2], srcA);
            float b1A = __shfl_sync(0xFFFFFFFFu, s[g][3], srcA);
            float a0B = __shfl_sync(0xFFFFFFFFu, s[g][0], srcB);
            float a1B = __shfl_sync(0xFFFFFFFFu, s[g][1], srcB);
            float b0B = __shfl_sync(0xFFFFFFFFu, s[g][2], srcB);
            float b1B = __shfl_sync(0xFFFFFFFFu, s[g][3], srcB);
            uint32_t pa[4];
            pa[0] = __float_as_uint(odd ? a1A : a0A);
            pa[1] = __float_as_uint(odd ? b1A : b0A);
            pa[2] = __float_as_uint(odd ? a1B : a0B);
            pa[3] = __float_as_uint(odd ? b1B : b0B);
            int k0 = g * 8 + q, k1 = g * 8 + q + 4;
#pragma unroll
            for (int nt = 0; nt < 16; nt++) {
                int dc = nt * 8 + r;
                uint32_t bf[2];
                bf[0] = __float_as_uint(Vst[k0 * VP + dc]);
                bf[1] = __float_as_uint(Vst[k1 * VP + dc]);
                mma1688(of[nt], pa, bf);
            }
        }
    }

    // epilogue: normalize + tf32-round (dense GEMM consumes rounded anyway)
    float li0 = 1.f / l0, li1 = 1.f / l1;
    int growA = qt * FQ + rA, growB = qt * FQ + rB;
#pragma unroll
    for (int nt = 0; nt < 16; nt++) {
        int col = h * HD + nt * 8 + 2 * q;
        *(float2*)(g_ctx + (size_t)(b * SEQ + growA) * HID + col) = make_float2(
            __uint_as_float(f2tf32(of[nt][0] * li0)),
            __uint_as_float(f2tf32(of[nt][1] * li0)));
        *(float2*)(g_ctx + (size_t)(b * SEQ + growB) * HID + col) = make_float2(
            __uint_as_float(f2tf32(of[nt][2] * li1)),
            __uint_as_float(f2tf32(of[nt][3] * li1)));
    }
}

// ---------------- launch ----------------
extern "C" void kernel_launch(void* const* d_in, const int* in_sizes, int n_in,
                              void* d_out, int out_size)
{
    const float* x    = (const float*)d_in[0];   // [B,S,H]
    const float* qkvw = (const float*)d_in[1];   // [H, 3H]
    const float* dw   = (const float*)d_in[2];   // [H, H]
    const float* rel  = (const float*)d_in[3];   // [32, 16]
    float* out = (float*)d_out;

    float *p_qkv, *p_ctx, *p_xr, *p_wqkvr, *p_dwr;
    cudaGetSymbolAddress((void**)&p_qkv,   g_qkv);
    cudaGetSymbolAddress((void**)&p_ctx,   g_ctx);
    cudaGetSymbolAddress((void**)&p_xr,    g_xr);
    cudaGetSymbolAddress((void**)&p_wqkvr, g_wqkvr);
    cudaGetSymbolAddress((void**)&p_dwr,   g_dwr);

    cudaFuncSetAttribute(gemm_mma, cudaFuncAttributeMaxDynamicSharedMemorySize, GEMM_SMEM);
    cudaFuncSetAttribute(flash_mma_kernel, cudaFuncAttributeMaxDynamicSharedMemorySize, FLASH_SMEM);

    // 0) pre-round operands to tf32; RoPE tables
    tf32_round_kernel<<<(BATCH * SEQ * HID / 4) / 256, 256>>>(x, p_xr);
    tf32_round_kernel<<<(HID * 3 * HID / 4) / 256, 256>>>(qkvw, p_wqkvr);
    tf32_round_kernel<<<(HID * HID / 4) / 256, 256>>>(dw, p_dwr);
    rope_table_kernel<<<(SEQ * 64) / 256, 256>>>();

    // 1) QKV GEMM (tf32 mma.sync, pre-rounded)
    gemm_mma<<<dim3(3 * HID / GBN, BATCH * SEQ / GBM), 256, GEMM_SMEM>>>(
        p_xr, p_wqkvr, p_qkv, BATCH * SEQ, 3 * HID, HID);

    // 2) RoPE + layout split + tf32 pre-round
    rope_split_kernel<<<(BATCH * SEQ * NHEADS * 64) / 256, 256>>>();

    // 3) bias table
    bias_kernel<<<(NHEADS * SEQ + 255) / 256, 256>>>(rel);

    // 4) flash attention (FA2-style tf32 mma, Q in regs)
    flash_mma_kernel<<<dim3(SEQ / FQ, NHEADS, BATCH), 256, FLASH_SMEM>>>();

    // 5) dense GEMM (tf32 mma.sync, pre-rounded ctx/dw)
    gemm_mma<<<dim3(HID / GBN, BATCH * SEQ / GBM), 256, GEMM_SMEM>>>(
        p_ctx, p_dwr, out, BATCH * SEQ, HID, HID);
}